// round 7
// baseline (speedup 1.0000x reference)
#include <cuda_runtime.h>
#include <cuda_bf16.h>
#include <cstdint>
#include <math.h>

#define D_MODEL 768
#define D_FF    2048
#define NE      8
#define T_TOK   2048
#define CAP     2048

// ======================= scratch (__device__ globals) =======================
__device__ int   g_count[NE];
__device__ int   g_fill[NE];
__device__ int   g_rows[NE * CAP];
__device__ float g_wts [NE * CAP];
__device__ int   g_topi[T_TOK * 2];
__device__ float g_topw[T_TOK * 2];

__device__ __align__(16) __nv_bfloat16 g_xhi[T_TOK * D_MODEL];
__device__ __align__(16) __nv_bfloat16 g_xlo[T_TOK * D_MODEL];
// h = silu(g)*u, split hi/lo: [E][CAP][D_FF]
__device__ __align__(16) __nv_bfloat16 g_h_hi[(size_t)NE * CAP * D_FF];
__device__ __align__(16) __nv_bfloat16 g_h_lo[(size_t)NE * CAP * D_FF];

// ======================= helpers =======================
__device__ __forceinline__ uint32_t smem_u32(const void* p) {
    uint32_t a;
    asm("{ .reg .u64 t; cvta.to.shared.u64 t, %1; cvt.u32.u64 %0, t; }" : "=r"(a) : "l"(p));
    return a;
}
__device__ __forceinline__ void ldsm4(uint32_t (&r)[4], uint32_t addr) {
    asm volatile("ldmatrix.sync.aligned.m8n8.x4.shared.b16 {%0,%1,%2,%3}, [%4];"
                 : "=r"(r[0]), "=r"(r[1]), "=r"(r[2]), "=r"(r[3]) : "r"(addr));
}
__device__ __forceinline__ void ldsm4t(uint32_t (&r)[4], uint32_t addr) {
    asm volatile("ldmatrix.sync.aligned.m8n8.x4.trans.shared.b16 {%0,%1,%2,%3}, [%4];"
                 : "=r"(r[0]), "=r"(r[1]), "=r"(r[2]), "=r"(r[3]) : "r"(addr));
}
__device__ __forceinline__ void mma16816(float (&d)[4], const uint32_t (&a)[4],
                                         uint32_t b0, uint32_t b1) {
    asm volatile(
        "mma.sync.aligned.m16n8k16.row.col.f32.bf16.bf16.f32 "
        "{%0,%1,%2,%3}, {%4,%5,%6,%7}, {%8,%9}, {%0,%1,%2,%3};"
        : "+f"(d[0]), "+f"(d[1]), "+f"(d[2]), "+f"(d[3])
        : "r"(a[0]), "r"(a[1]), "r"(a[2]), "r"(a[3]), "r"(b0), "r"(b1));
}
#define CP16(dst, src)  asm volatile("cp.async.cg.shared.global [%0], [%1], 16;" :: "r"(dst), "l"(src))
#define CPCOMMIT()      asm volatile("cp.async.commit_group;" ::: "memory")
#define CPWAIT0()       asm volatile("cp.async.wait_group 0;" ::: "memory")

__device__ __forceinline__ uint32_t pack2(__nv_bfloat16 a, __nv_bfloat16 b) {
    __nv_bfloat162 p = __halves2bfloat162(a, b);
    return *reinterpret_cast<uint32_t*>(&p);
}
// 8 fp32 -> 8 hi bf16 + 8 lo bf16 (packed as uint4 each)
__device__ __forceinline__ void cvt8(const float4& f0, const float4& f1,
                                     uint4& hi, uint4& lo) {
    float f[8] = {f0.x, f0.y, f0.z, f0.w, f1.x, f1.y, f1.z, f1.w};
    __nv_bfloat16 h[8], l[8];
#pragma unroll
    for (int i = 0; i < 8; i++) {
        h[i] = __float2bfloat16(f[i]);
        l[i] = __float2bfloat16(f[i] - __bfloat162float(h[i]));
    }
    hi = make_uint4(pack2(h[0], h[1]), pack2(h[2], h[3]), pack2(h[4], h[5]), pack2(h[6], h[7]));
    lo = make_uint4(pack2(l[0], l[1]), pack2(l[2], l[3]), pack2(l[4], l[5]), pack2(l[6], l[7]));
}

// ======================= small kernels =======================
__global__ void k_reset(float* __restrict__ out, int out_n) {
    int i = blockIdx.x * blockDim.x + threadIdx.x;
    if (i < NE) { g_count[i] = 0; g_fill[i] = 0; }
    for (int j = i; j < out_n; j += gridDim.x * blockDim.x) out[j] = 0.0f;
}

__global__ void k_router(const float* __restrict__ x, const float* __restrict__ gw) {
    int t = blockIdx.x * (blockDim.x >> 5) + (threadIdx.x >> 5);
    int lane = threadIdx.x & 31;
    if (t >= T_TOK) return;
    const float* xr = x + (size_t)t * D_MODEL;
    float acc[NE];
#pragma unroll
    for (int e = 0; e < NE; e++) acc[e] = 0.0f;
    for (int d = lane; d < D_MODEL; d += 32) {
        float xv = xr[d];
        const float* g = gw + (size_t)d * NE;
#pragma unroll
        for (int e = 0; e < NE; e++) acc[e] += xv * g[e];
    }
#pragma unroll
    for (int off = 16; off > 0; off >>= 1)
#pragma unroll
        for (int e = 0; e < NE; e++) acc[e] += __shfl_xor_sync(0xFFFFFFFFu, acc[e], off);

    if (lane == 0) {
        int i0 = 0;
#pragma unroll
        for (int e = 1; e < NE; e++) if (acc[e] > acc[i0]) i0 = e;
        int i1 = -1; float b = -1e30f;
#pragma unroll
        for (int e = 0; e < NE; e++) if (e != i0 && acc[e] > b) { b = acc[e]; i1 = e; }
        float w1 = expf(acc[i1] - acc[i0]);
        float s  = 1.0f + w1;
        g_topi[t * 2 + 0] = i0;  g_topw[t * 2 + 0] = 1.0f / s;
        g_topi[t * 2 + 1] = i1;  g_topw[t * 2 + 1] = w1 / s;
        atomicAdd(&g_count[i0], 1);
        atomicAdd(&g_count[i1], 1);
    }
}

__global__ void k_scatter() {
    int idx = blockIdx.x * blockDim.x + threadIdx.x;
    if (idx >= T_TOK * 2) return;
    int e = g_topi[idx];
    int p = atomicAdd(&g_fill[e], 1);
    g_rows[e * CAP + p] = idx >> 1;
    g_wts [e * CAP + p] = g_topw[idx];
}

__global__ void k_cvt_x(const float* __restrict__ x) {
    int i = blockIdx.x * blockDim.x + threadIdx.x;
    if (i >= T_TOK * D_MODEL) return;
    float v = x[i];
    __nv_bfloat16 hi = __float2bfloat16(v);
    g_xhi[i] = hi;
    g_xlo[i] = __float2bfloat16(v - __bfloat162float(hi));
}

// ======================= HMMA GEMM kernels =======================
// Tile: M=128 x N=64, K-chunk 32. 256 threads = 8 warps in 4(m) x 2(n).
// A smem row stride 40 bf16 (80B), B 72 bf16 (144B) -> ldmatrix conflict-free, 16B-aligned.
#define SA 40
#define SB 72

// A: double-buffered cp.async stages (hi+lo = 20480B each). B: single buffer,
// register-prefetched fp32 -> converted at store time.
static constexpr int STG_A  = 20480;                 // AH 10240 + AL 10240
static constexpr int OFF_GH = 2 * STG_A;             // 40960
static constexpr int OFF_GL = OFF_GH + 4608;
static constexpr int OFF_UH = OFF_GL + 4608;
static constexpr int OFF_UL = OFF_UH + 4608;
static constexpr int SMEM_GU = OFF_UL + 4608;        // 59392
static constexpr int OFF_BH = 2 * STG_A;
static constexpr int OFF_BL = OFF_BH + 4608;
static constexpr int SMEM_DN = OFF_BL + 4608;        // 50176

// h = silu(x@Wg) * (x@Wu)   (weights fp32 native [k][n], converted inline)
__global__ void __launch_bounds__(256) k_hmma_gu(
    const float* __restrict__ wg, const float* __restrict__ wu)
{
    int e   = blockIdx.z;
    int cnt = g_count[e];
    int r0  = blockIdx.y * 128;
    if (r0 >= cnt) return;
    int n0  = blockIdx.x * 64;

    extern __shared__ char smem[];
    uint32_t sb = smem_u32(smem);

    int tid = threadIdx.x, lane = tid & 31, wid = tid >> 5;
    int wm = wid >> 1, wn = wid & 1;

    // --- A loader (cp.async) ---
    int arow = tid >> 1, ahalf = tid & 1;
    int slotA = r0 + arow;
    int tok = (slotA < cnt) ? g_rows[e * CAP + slotA] : 0;
    const __nv_bfloat16* pAh = g_xhi + (size_t)tok * D_MODEL + ahalf * 16;
    const __nv_bfloat16* pAl = g_xlo + (size_t)tok * D_MODEL + ahalf * 16;
    uint32_t aoff = (uint32_t)(arow * SA + ahalf * 16) * 2;

    auto load_A = [&](int c, int s) {
        uint32_t base = sb + s * STG_A;
        int ka = c * 32;
        CP16(base + aoff,              pAh + ka);
        CP16(base + aoff + 16,         pAh + ka + 8);
        CP16(base + 10240 + aoff,      pAl + ka);
        CP16(base + 10240 + aoff + 16, pAl + ka + 8);
        CPCOMMIT();
    };

    // --- B loader (LDG fp32 -> regs -> convert -> smem) ---
    int brow = tid >> 3, bq = tid & 7;      // 32 k-rows x 8 col-quads
    const float* pG = wg + (size_t)e * D_MODEL * D_FF + (size_t)brow * D_FF + n0 + bq * 8;
    const float* pU = wu + (size_t)e * D_MODEL * D_FF + (size_t)brow * D_FF + n0 + bq * 8;
    uint32_t bsoff = (uint32_t)(brow * SB + bq * 8) * 2;
    uint4* dGh = (uint4*)(smem + OFF_GH + bsoff);
    uint4* dGl = (uint4*)(smem + OFF_GL + bsoff);
    uint4* dUh = (uint4*)(smem + OFF_UH + bsoff);
    uint4* dUl = (uint4*)(smem + OFF_UL + bsoff);

    float ag[2][4][4], au[2][4][4];
#pragma unroll
    for (int i = 0; i < 2; i++)
#pragma unroll
        for (int j = 0; j < 4; j++)
#pragma unroll
            for (int q = 0; q < 4; q++) { ag[i][j][q] = 0.0f; au[i][j][q] = 0.0f; }

    const int NC = D_MODEL / 32;            // 24

    // prologue: chunk 0 in flight
    load_A(0, 0);
    float4 rg0 = *(const float4*)pG,       rg1 = *(const float4*)(pG + 4);
    float4 ru0 = *(const float4*)pU,       ru1 = *(const float4*)(pU + 4);

    for (int c = 0; c < NC; c++) {
        // store B(c) regs -> smem (compute c-1 finished at prior sync)
        { uint4 hi, lo; cvt8(rg0, rg1, hi, lo); *dGh = hi; *dGl = lo; }
        { uint4 hi, lo; cvt8(ru0, ru1, hi, lo); *dUh = hi; *dUl = lo; }
        CPWAIT0();                          // A(c) landed
        __syncthreads();
        if (c + 1 < NC) {                   // prefetch c+1 (overlaps compute)
            load_A(c + 1, (c + 1) & 1);
            size_t kb = (size_t)(c + 1) * 32 * D_FF;
            rg0 = *(const float4*)(pG + kb); rg1 = *(const float4*)(pG + kb + 4);
            ru0 = *(const float4*)(pU + kb); ru1 = *(const float4*)(pU + kb + 4);
        }

        uint32_t abase = sb + (c & 1) * STG_A;
        uint32_t bAh = abase, bAl = abase + 10240;
        uint32_t bGh = sb + OFF_GH, bGl = sb + OFF_GL;
        uint32_t bUh = sb + OFF_UH, bUl = sb + OFF_UL;

#pragma unroll
        for (int kk = 0; kk < 32; kk += 16) {
            uint32_t ah[2][4], al[2][4];
#pragma unroll
            for (int mf = 0; mf < 2; mf++) {
                uint32_t ro = wm * 32 + mf * 16 + (lane & 15);
                uint32_t co = kk + (lane >> 4) * 8;
                ldsm4(ah[mf], bAh + (ro * SA + co) * 2);
                ldsm4(al[mf], bAl + (ro * SA + co) * 2);
            }
            uint32_t kr = kk + (lane & 7) + ((lane >> 4) & 1) * 8;
            uint32_t ncol = wn * 32 + ((lane >> 3) & 1) * 8;
            // ---- gate ----
            {
                uint32_t bh[4][2], bl[4][2], r4[4];
#pragma unroll
                for (int p = 0; p < 2; p++) {
                    uint32_t off = (kr * SB + ncol + p * 16) * 2;
                    ldsm4t(r4, bGh + off);
                    bh[p*2][0] = r4[0]; bh[p*2+1][0] = r4[1]; bh[p*2][1] = r4[2]; bh[p*2+1][1] = r4[3];
                    ldsm4t(r4, bGl + off);
                    bl[p*2][0] = r4[0]; bl[p*2+1][0] = r4[1]; bl[p*2][1] = r4[2]; bl[p*2+1][1] = r4[3];
                }
#pragma unroll
                for (int mf = 0; mf < 2; mf++)
#pragma unroll
                    for (int nf = 0; nf < 4; nf++) {
                        mma16816(ag[mf][nf], ah[mf], bh[nf][0], bh[nf][1]);
                        mma16816(ag[mf][nf], ah[mf], bl[nf][0], bl[nf][1]);
                        mma16816(ag[mf][nf], al[mf], bh[nf][0], bh[nf][1]);
                    }
            }
            // ---- up ----
            {
                uint32_t bh[4][2], bl[4][2], r4[4];
#pragma unroll
                for (int p = 0; p < 2; p++) {
                    uint32_t off = (kr * SB + ncol + p * 16) * 2;
                    ldsm4t(r4, bUh + off);
                    bh[p*2][0] = r4[0]; bh[p*2+1][0] = r4[1]; bh[p*2][1] = r4[2]; bh[p*2+1][1] = r4[3];
                    ldsm4t(r4, bUl + off);
                    bl[p*2][0] = r4[0]; bl[p*2+1][0] = r4[1]; bl[p*2][1] = r4[2]; bl[p*2+1][1] = r4[3];
                }
#pragma unroll
                for (int mf = 0; mf < 2; mf++)
#pragma unroll
                    for (int nf = 0; nf < 4; nf++) {
                        mma16816(au[mf][nf], ah[mf], bh[nf][0], bh[nf][1]);
                        mma16816(au[mf][nf], ah[mf], bl[nf][0], bl[nf][1]);
                        mma16816(au[mf][nf], al[mf], bh[nf][0], bh[nf][1]);
                    }
            }
        }
        __syncthreads();
    }

    // ---- epilogue: h = silu(g)*u -> split bf16 ----
    int lr = lane >> 2, lc = (lane & 3) * 2;
#pragma unroll
    for (int mf = 0; mf < 2; mf++)
#pragma unroll
        for (int half = 0; half < 2; half++) {
            int slot = r0 + wm * 32 + mf * 16 + lr + half * 8;
            if (slot >= cnt) continue;
            size_t base = ((size_t)e * CAP + slot) * D_FF + n0 + wn * 32 + lc;
#pragma unroll
            for (int nf = 0; nf < 4; nf++) {
                float g0 = ag[mf][nf][half * 2 + 0], g1 = ag[mf][nf][half * 2 + 1];
                float u0 = au[mf][nf][half * 2 + 0], u1 = au[mf][nf][half * 2 + 1];
                float h0 = (g0 / (1.0f + __expf(-g0))) * u0;
                float h1 = (g1 / (1.0f + __expf(-g1))) * u1;
                __nv_bfloat16 h0h = __float2bfloat16(h0);
                __nv_bfloat16 h1h = __float2bfloat16(h1);
                __nv_bfloat16 h0l = __float2bfloat16(h0 - __bfloat162float(h0h));
                __nv_bfloat16 h1l = __float2bfloat16(h1 - __bfloat162float(h1h));
                *(__nv_bfloat162*)(g_h_hi + base + nf * 8) = __halves2bfloat162(h0h, h1h);
                *(__nv_bfloat162*)(g_h_lo + base + nf * 8) = __halves2bfloat162(h0l, h1l);
            }
        }
}

// out[token] += gate_wt * (h @ Wd)
__global__ void __launch_bounds__(256) k_hmma_down(
    const float* __restrict__ wd, float* __restrict__ out)
{
    int e   = blockIdx.z;
    int cnt = g_count[e];
    int r0  = blockIdx.y * 128;
    if (r0 >= cnt) return;
    int n0  = blockIdx.x * 64;

    extern __shared__ char smem[];
    uint32_t sb = smem_u32(smem);

    int tid = threadIdx.x, lane = tid & 31, wid = tid >> 5;
    int wm = wid >> 1, wn = wid & 1;

    int arow = tid >> 1, ahalf = tid & 1;
    int slotA = r0 + arow;
    int asafe = (slotA < cnt) ? slotA : 0;
    size_t hrow = ((size_t)e * CAP + asafe) * D_FF + ahalf * 16;
    const __nv_bfloat16* pAh = g_h_hi + hrow;
    const __nv_bfloat16* pAl = g_h_lo + hrow;
    uint32_t aoff = (uint32_t)(arow * SA + ahalf * 16) * 2;

    auto load_A = [&](int c, int s) {
        uint32_t base = sb + s * STG_A;
        int ka = c * 32;
        CP16(base + aoff,              pAh + ka);
        CP16(base + aoff + 16,         pAh + ka + 8);
        CP16(base + 10240 + aoff,      pAl + ka);
        CP16(base + 10240 + aoff + 16, pAl + ka + 8);
        CPCOMMIT();
    };

    int brow = tid >> 3, bq = tid & 7;
    const float* pB = wd + (size_t)e * D_FF * D_MODEL + (size_t)brow * D_MODEL + n0 + bq * 8;
    uint32_t bsoff = (uint32_t)(brow * SB + bq * 8) * 2;
    uint4* dBh = (uint4*)(smem + OFF_BH + bsoff);
    uint4* dBl = (uint4*)(smem + OFF_BL + bsoff);

    float ac[2][4][4];
#pragma unroll
    for (int i = 0; i < 2; i++)
#pragma unroll
        for (int j = 0; j < 4; j++)
#pragma unroll
            for (int q = 0; q < 4; q++) ac[i][j][q] = 0.0f;

    const int NC = D_FF / 32;               // 64

    load_A(0, 0);
    float4 rb0 = *(const float4*)pB, rb1 = *(const float4*)(pB + 4);

    for (int c = 0; c < NC; c++) {
        { uint4 hi, lo; cvt8(rb0, rb1, hi, lo); *dBh = hi; *dBl = lo; }
        CPWAIT0();
        __syncthreads();
        if (c + 1 < NC) {
            load_A(c + 1, (c + 1) & 1);
            size_t kb = (size_t)(c + 1) * 32 * D_MODEL;
            rb0 = *(const float4*)(pB + kb); rb1 = *(const float4*)(pB + kb + 4);
        }

        uint32_t abase = sb + (c & 1) * STG_A;
        uint32_t bAh = abase, bAl = abase + 10240;
        uint32_t bBh = sb + OFF_BH, bBl = sb + OFF_BL;

#pragma unroll
        for (int kk = 0; kk < 32; kk += 16) {
            uint32_t ah[2][4], al[2][4];
#pragma unroll
            for (int mf = 0; mf < 2; mf++) {
                uint32_t ro = wm * 32 + mf * 16 + (lane & 15);
                uint32_t co = kk + (lane >> 4) * 8;
                ldsm4(ah[mf], bAh + (ro * SA + co) * 2);
                ldsm4(al[mf], bAl + (ro * SA + co) * 2);
            }
            uint32_t kr = kk + (lane & 7) + ((lane >> 4) & 1) * 8;
            uint32_t ncol = wn * 32 + ((lane >> 3) & 1) * 8;
            uint32_t bh[4][2], bl[4][2], r4[4];
#pragma unroll
            for (int p = 0; p < 2; p++) {
                uint32_t off = (kr * SB + ncol + p * 16) * 2;
                ldsm4t(r4, bBh + off);
                bh[p*2][0] = r4[0]; bh[p*2+1][0] = r4[1]; bh[p*2][1] = r4[2]; bh[p*2+1][1] = r4[3];
                ldsm4t(r4, bBl + off);
                bl[p*2][0] = r4[0]; bl[p*2+1][0] = r4[1]; bl[p*2][1] = r4[2]; bl[p*2+1][1] = r4[3];
            }
#pragma unroll
            for (int mf = 0; mf < 2; mf++)
#pragma unroll
                for (int nf = 0; nf < 4; nf++) {
                    mma16816(ac[mf][nf], ah[mf], bh[nf][0], bh[nf][1]);
                    mma16816(ac[mf][nf], ah[mf], bl[nf][0], bl[nf][1]);
                    mma16816(ac[mf][nf], al[mf], bh[nf][0], bh[nf][1]);
                }
        }
        __syncthreads();
    }

    // ---- epilogue: weighted atomic scatter-add ----
    int lr = lane >> 2, lc = (lane & 3) * 2;
#pragma unroll
    for (int mf = 0; mf < 2; mf++)
#pragma unroll
        for (int half = 0; half < 2; half++) {
            int slot = r0 + wm * 32 + mf * 16 + lr + half * 8;
            if (slot >= cnt) continue;
            int   tok = g_rows[e * CAP + slot];
            float w   = g_wts [e * CAP + slot];
            float* orow = out + (size_t)tok * D_MODEL + n0 + wn * 32 + lc;
#pragma unroll
            for (int nf = 0; nf < 4; nf++) {
                atomicAdd(&orow[nf * 8 + 0], ac[mf][nf][half * 2 + 0] * w);
                atomicAdd(&orow[nf * 8 + 1], ac[mf][nf][half * 2 + 1] * w);
            }
        }
}

// ======================= launch =======================
extern "C" void kernel_launch(void* const* d_in, const int* in_sizes, int n_in,
                              void* d_out, int out_size) {
    const float* x      = (const float*)d_in[0];   // [2,1024,768]
    const float* gate_w = (const float*)d_in[1];   // [768,8]
    const float* w_gate = (const float*)d_in[2];   // [8,768,2048]
    const float* w_up   = (const float*)d_in[3];   // [8,768,2048]
    const float* w_down = (const float*)d_in[4];   // [8,2048,768]
    float* out = (float*)d_out;

    cudaFuncSetAttribute(k_hmma_gu,   cudaFuncAttributeMaxDynamicSharedMemorySize, SMEM_GU);
    cudaFuncSetAttribute(k_hmma_down, cudaFuncAttributeMaxDynamicSharedMemorySize, SMEM_DN);

    k_reset<<<512, 256>>>(out, out_size);
    k_router<<<T_TOK / 8, 256>>>(x, gate_w);
    k_scatter<<<(T_TOK * 2 + 255) / 256, 256>>>();
    k_cvt_x<<<(T_TOK * D_MODEL + 255) / 256, 256>>>(x);

    {   // fused gate/up HMMA + SiLU
        dim3 grid(D_FF / 64, CAP / 128, NE);
        k_hmma_gu<<<grid, 256, SMEM_GU>>>(w_gate, w_up);
    }
    {   // down HMMA + weighted scatter-add
        dim3 grid(D_MODEL / 64, CAP / 128, NE);
        k_hmma_down<<<grid, 256, SMEM_DN>>>(w_down, out);
    }
}

// round 8
// speedup vs baseline: 1.0843x; 1.0843x over previous
#include <cuda_runtime.h>
#include <cuda_bf16.h>
#include <cstdint>
#include <math.h>

#define D_MODEL 768
#define D_FF    2048
#define NE      8
#define T_TOK   2048
#define CAP     2048

// ======================= scratch (__device__ globals) =======================
__device__ int   g_count[NE];
__device__ int   g_fill[NE];
__device__ int   g_rows[NE * CAP];
__device__ float g_wts [NE * CAP];
__device__ int   g_topi[T_TOK * 2];
__device__ float g_topw[T_TOK * 2];

__device__ __align__(16) __nv_bfloat16 g_xhi[T_TOK * D_MODEL];
__device__ __align__(16) __nv_bfloat16 g_xlo[T_TOK * D_MODEL];
// h = silu(g)*u, split hi/lo: [E][CAP][D_FF]
__device__ __align__(16) __nv_bfloat16 g_h_hi[(size_t)NE * CAP * D_FF];
__device__ __align__(16) __nv_bfloat16 g_h_lo[(size_t)NE * CAP * D_FF];

// ======================= helpers =======================
__device__ __forceinline__ uint32_t smem_u32(const void* p) {
    uint32_t a;
    asm("{ .reg .u64 t; cvta.to.shared.u64 t, %1; cvt.u32.u64 %0, t; }" : "=r"(a) : "l"(p));
    return a;
}
__device__ __forceinline__ void ldsm4(uint32_t (&r)[4], uint32_t addr) {
    asm volatile("ldmatrix.sync.aligned.m8n8.x4.shared.b16 {%0,%1,%2,%3}, [%4];"
                 : "=r"(r[0]), "=r"(r[1]), "=r"(r[2]), "=r"(r[3]) : "r"(addr));
}
__device__ __forceinline__ void ldsm4t(uint32_t (&r)[4], uint32_t addr) {
    asm volatile("ldmatrix.sync.aligned.m8n8.x4.trans.shared.b16 {%0,%1,%2,%3}, [%4];"
                 : "=r"(r[0]), "=r"(r[1]), "=r"(r[2]), "=r"(r[3]) : "r"(addr));
}
__device__ __forceinline__ void mma16816(float (&d)[4], const uint32_t (&a)[4],
                                         uint32_t b0, uint32_t b1) {
    asm volatile(
        "mma.sync.aligned.m16n8k16.row.col.f32.bf16.bf16.f32 "
        "{%0,%1,%2,%3}, {%4,%5,%6,%7}, {%8,%9}, {%0,%1,%2,%3};"
        : "+f"(d[0]), "+f"(d[1]), "+f"(d[2]), "+f"(d[3])
        : "r"(a[0]), "r"(a[1]), "r"(a[2]), "r"(a[3]), "r"(b0), "r"(b1));
}

__device__ __forceinline__ uint32_t pack2(__nv_bfloat16 a, __nv_bfloat16 b) {
    __nv_bfloat162 p = __halves2bfloat162(a, b);
    return *reinterpret_cast<uint32_t*>(&p);
}
// 8 fp32 -> 8 hi bf16 + 8 lo bf16 (packed as uint4 each)
__device__ __forceinline__ void cvt8(const float4& f0, const float4& f1,
                                     uint4& hi, uint4& lo) {
    float f[8] = {f0.x, f0.y, f0.z, f0.w, f1.x, f1.y, f1.z, f1.w};
    __nv_bfloat16 h[8], l[8];
#pragma unroll
    for (int i = 0; i < 8; i++) {
        h[i] = __float2bfloat16(f[i]);
        l[i] = __float2bfloat16(f[i] - __bfloat162float(h[i]));
    }
    hi = make_uint4(pack2(h[0], h[1]), pack2(h[2], h[3]), pack2(h[4], h[5]), pack2(h[6], h[7]));
    lo = make_uint4(pack2(l[0], l[1]), pack2(l[2], l[3]), pack2(l[4], l[5]), pack2(l[6], l[7]));
}

// ======================= small kernels =======================
__global__ void k_reset(float* __restrict__ out, int out_n) {
    int i = blockIdx.x * blockDim.x + threadIdx.x;
    if (i < NE) { g_count[i] = 0; g_fill[i] = 0; }
    for (int j = i; j < out_n; j += gridDim.x * blockDim.x) out[j] = 0.0f;
}

__global__ void k_router(const float* __restrict__ x, const float* __restrict__ gw) {
    int t = blockIdx.x * (blockDim.x >> 5) + (threadIdx.x >> 5);
    int lane = threadIdx.x & 31;
    if (t >= T_TOK) return;
    const float* xr = x + (size_t)t * D_MODEL;
    float acc[NE];
#pragma unroll
    for (int e = 0; e < NE; e++) acc[e] = 0.0f;
    for (int d = lane; d < D_MODEL; d += 32) {
        float xv = xr[d];
        const float* g = gw + (size_t)d * NE;
#pragma unroll
        for (int e = 0; e < NE; e++) acc[e] += xv * g[e];
    }
#pragma unroll
    for (int off = 16; off > 0; off >>= 1)
#pragma unroll
        for (int e = 0; e < NE; e++) acc[e] += __shfl_xor_sync(0xFFFFFFFFu, acc[e], off);

    if (lane == 0) {
        int i0 = 0;
#pragma unroll
        for (int e = 1; e < NE; e++) if (acc[e] > acc[i0]) i0 = e;
        int i1 = -1; float b = -1e30f;
#pragma unroll
        for (int e = 0; e < NE; e++) if (e != i0 && acc[e] > b) { b = acc[e]; i1 = e; }
        float w1 = expf(acc[i1] - acc[i0]);
        float s  = 1.0f + w1;
        g_topi[t * 2 + 0] = i0;  g_topw[t * 2 + 0] = 1.0f / s;
        g_topi[t * 2 + 1] = i1;  g_topw[t * 2 + 1] = w1 / s;
        atomicAdd(&g_count[i0], 1);
        atomicAdd(&g_count[i1], 1);
    }
}

__global__ void k_scatter() {
    int idx = blockIdx.x * blockDim.x + threadIdx.x;
    if (idx >= T_TOK * 2) return;
    int e = g_topi[idx];
    int p = atomicAdd(&g_fill[e], 1);
    g_rows[e * CAP + p] = idx >> 1;
    g_wts [e * CAP + p] = g_topw[idx];
}

// vectorized: 4 fp32 -> 4 hi + 4 lo bf16 per thread
__global__ void k_cvt_x(const float* __restrict__ x) {
    int i = blockIdx.x * blockDim.x + threadIdx.x;
    if (i >= T_TOK * D_MODEL / 4) return;
    float4 f = reinterpret_cast<const float4*>(x)[i];
    float v[4] = {f.x, f.y, f.z, f.w};
    __nv_bfloat16 h[4], l[4];
#pragma unroll
    for (int j = 0; j < 4; j++) {
        h[j] = __float2bfloat16(v[j]);
        l[j] = __float2bfloat16(v[j] - __bfloat162float(h[j]));
    }
    reinterpret_cast<uint2*>(g_xhi)[i] = make_uint2(pack2(h[0], h[1]), pack2(h[2], h[3]));
    reinterpret_cast<uint2*>(g_xlo)[i] = make_uint2(pack2(l[0], l[1]), pack2(l[2], l[3]));
}

// ======================= HMMA GEMM kernels =======================
// Tile: M=128 x N=64, K-chunk 32. 256 threads = 8 warps in 4(m) x 2(n).
// A smem row stride 40 bf16 (80B), B 72 bf16 (144B) -> ldmatrix conflict-free.
#define SA 40
#define SB 72

// h = silu(x@Wg) * (x@Wu)  (weights read fp32 [k][n] native layout, converted inline)
__global__ void __launch_bounds__(256, 2) k_hmma_gu(
    const float* __restrict__ wg, const float* __restrict__ wu)
{
    int e   = blockIdx.z;
    int cnt = g_count[e];
    int r0  = blockIdx.y * 128;
    if (r0 >= cnt) return;
    int n0  = blockIdx.x * 64;

    __shared__ __nv_bfloat16 sAh[128 * SA], sAl[128 * SA];
    __shared__ __nv_bfloat16 sGh[32 * SB], sGl[32 * SB];
    __shared__ __nv_bfloat16 sUh[32 * SB], sUl[32 * SB];

    int tid = threadIdx.x, lane = tid & 31, wid = tid >> 5;
    int wm = wid >> 1, wn = wid & 1;

    // --- loader setup ---
    int arow = tid >> 1, ahalf = tid & 1;
    int slotA = r0 + arow;
    int tok = (slotA < cnt) ? g_rows[e * CAP + slotA] : 0;
    const __nv_bfloat16* pAh = g_xhi + (size_t)tok * D_MODEL + ahalf * 16;
    const __nv_bfloat16* pAl = g_xlo + (size_t)tok * D_MODEL + ahalf * 16;
    __nv_bfloat16* dAh = sAh + arow * SA + ahalf * 16;
    __nv_bfloat16* dAl = sAl + arow * SA + ahalf * 16;

    int brow = tid >> 3, bq = tid & 7;      // 32 k-rows x 8 col-quads
    const float* pG = wg + (size_t)e * D_MODEL * D_FF + (size_t)brow * D_FF + n0 + bq * 8;
    const float* pU = wu + (size_t)e * D_MODEL * D_FF + (size_t)brow * D_FF + n0 + bq * 8;
    uint4* dGh = (uint4*)(sGh + brow * SB + bq * 8);
    uint4* dGl = (uint4*)(sGl + brow * SB + bq * 8);
    uint4* dUh = (uint4*)(sUh + brow * SB + bq * 8);
    uint4* dUl = (uint4*)(sUl + brow * SB + bq * 8);

    uint32_t bAh = smem_u32(sAh), bAl = smem_u32(sAl);
    uint32_t bGh = smem_u32(sGh), bGl = smem_u32(sGl);
    uint32_t bUh = smem_u32(sUh), bUl = smem_u32(sUl);

    float ag[2][4][4], au[2][4][4];
#pragma unroll
    for (int i = 0; i < 2; i++)
#pragma unroll
        for (int j = 0; j < 4; j++)
#pragma unroll
            for (int q = 0; q < 4; q++) { ag[i][j][q] = 0.0f; au[i][j][q] = 0.0f; }

    for (int c = 0; c < D_MODEL / 32; c++) {      // 24 chunks
        int k0 = c * 32;
        if (c > 0) __syncthreads();
        // A fill: 16 bf16 per thread per precision
        *(uint4*)dAh       = *(const uint4*)(pAh + k0);
        *(uint4*)(dAh + 8) = *(const uint4*)(pAh + k0 + 8);
        *(uint4*)dAl       = *(const uint4*)(pAl + k0);
        *(uint4*)(dAl + 8) = *(const uint4*)(pAl + k0 + 8);
        // B fill: 8 fp32 -> hi/lo bf16 per matrix
        {
            const float* s = pG + (size_t)k0 * D_FF;
            float4 f0 = *(const float4*)s, f1 = *(const float4*)(s + 4);
            uint4 hi, lo; cvt8(f0, f1, hi, lo);
            *dGh = hi; *dGl = lo;
        }
        {
            const float* s = pU + (size_t)k0 * D_FF;
            float4 f0 = *(const float4*)s, f1 = *(const float4*)(s + 4);
            uint4 hi, lo; cvt8(f0, f1, hi, lo);
            *dUh = hi; *dUl = lo;
        }
        __syncthreads();

#pragma unroll
        for (int kk = 0; kk < 32; kk += 16) {
            uint32_t ah[2][4], al[2][4];
#pragma unroll
            for (int mf = 0; mf < 2; mf++) {
                uint32_t ro = wm * 32 + mf * 16 + (lane & 15);
                uint32_t co = kk + (lane >> 4) * 8;
                ldsm4(ah[mf], bAh + (ro * SA + co) * 2);
                ldsm4(al[mf], bAl + (ro * SA + co) * 2);
            }
            uint32_t kr = kk + (lane & 7) + ((lane >> 4) & 1) * 8;
            uint32_t ncol = wn * 32 + ((lane >> 3) & 1) * 8;
            // ---- gate ----
            {
                uint32_t bh[4][2], bl[4][2], r4[4];
#pragma unroll
                for (int p = 0; p < 2; p++) {
                    uint32_t off = (kr * SB + ncol + p * 16) * 2;
                    ldsm4t(r4, bGh + off);
                    bh[p*2][0] = r4[0]; bh[p*2+1][0] = r4[1]; bh[p*2][1] = r4[2]; bh[p*2+1][1] = r4[3];
                    ldsm4t(r4, bGl + off);
                    bl[p*2][0] = r4[0]; bl[p*2+1][0] = r4[1]; bl[p*2][1] = r4[2]; bl[p*2+1][1] = r4[3];
                }
#pragma unroll
                for (int mf = 0; mf < 2; mf++)
#pragma unroll
                    for (int nf = 0; nf < 4; nf++) {
                        mma16816(ag[mf][nf], ah[mf], bh[nf][0], bh[nf][1]);
                        mma16816(ag[mf][nf], ah[mf], bl[nf][0], bl[nf][1]);
                        mma16816(ag[mf][nf], al[mf], bh[nf][0], bh[nf][1]);
                    }
            }
            // ---- up ----
            {
                uint32_t bh[4][2], bl[4][2], r4[4];
#pragma unroll
                for (int p = 0; p < 2; p++) {
                    uint32_t off = (kr * SB + ncol + p * 16) * 2;
                    ldsm4t(r4, bUh + off);
                    bh[p*2][0] = r4[0]; bh[p*2+1][0] = r4[1]; bh[p*2][1] = r4[2]; bh[p*2+1][1] = r4[3];
                    ldsm4t(r4, bUl + off);
                    bl[p*2][0] = r4[0]; bl[p*2+1][0] = r4[1]; bl[p*2][1] = r4[2]; bl[p*2+1][1] = r4[3];
                }
#pragma unroll
                for (int mf = 0; mf < 2; mf++)
#pragma unroll
                    for (int nf = 0; nf < 4; nf++) {
                        mma16816(au[mf][nf], ah[mf], bh[nf][0], bh[nf][1]);
                        mma16816(au[mf][nf], ah[mf], bl[nf][0], bl[nf][1]);
                        mma16816(au[mf][nf], al[mf], bh[nf][0], bh[nf][1]);
                    }
            }
        }
    }

    // ---- epilogue: h = silu(g)*u -> split bf16 ----
    int lr = lane >> 2, lc = (lane & 3) * 2;
#pragma unroll
    for (int mf = 0; mf < 2; mf++)
#pragma unroll
        for (int half = 0; half < 2; half++) {
            int slot = r0 + wm * 32 + mf * 16 + lr + half * 8;
            if (slot >= cnt) continue;
            size_t base = ((size_t)e * CAP + slot) * D_FF + n0 + wn * 32 + lc;
#pragma unroll
            for (int nf = 0; nf < 4; nf++) {
                float g0 = ag[mf][nf][half * 2 + 0], g1 = ag[mf][nf][half * 2 + 1];
                float u0 = au[mf][nf][half * 2 + 0], u1 = au[mf][nf][half * 2 + 1];
                float h0 = (g0 / (1.0f + __expf(-g0))) * u0;
                float h1 = (g1 / (1.0f + __expf(-g1))) * u1;
                __nv_bfloat16 h0h = __float2bfloat16(h0);
                __nv_bfloat16 h1h = __float2bfloat16(h1);
                __nv_bfloat16 h0l = __float2bfloat16(h0 - __bfloat162float(h0h));
                __nv_bfloat16 h1l = __float2bfloat16(h1 - __bfloat162float(h1h));
                *(__nv_bfloat162*)(g_h_hi + base + nf * 8) = __halves2bfloat162(h0h, h1h);
                *(__nv_bfloat162*)(g_h_lo + base + nf * 8) = __halves2bfloat162(h0l, h1l);
            }
        }
}

// out[token] += gate_wt * (h @ Wd)
__global__ void __launch_bounds__(256, 2) k_hmma_down(
    const float* __restrict__ wd, float* __restrict__ out)
{
    int e   = blockIdx.z;
    int cnt = g_count[e];
    int r0  = blockIdx.y * 128;
    if (r0 >= cnt) return;
    int n0  = blockIdx.x * 64;

    __shared__ __nv_bfloat16 sAh[128 * SA], sAl[128 * SA];
    __shared__ __nv_bfloat16 sBh[32 * SB], sBl[32 * SB];

    int tid = threadIdx.x, lane = tid & 31, wid = tid >> 5;
    int wm = wid >> 1, wn = wid & 1;

    int arow = tid >> 1, ahalf = tid & 1;
    int slotA = r0 + arow;
    int asafe = (slotA < cnt) ? slotA : 0;
    size_t hrow = ((size_t)e * CAP + asafe) * D_FF + ahalf * 16;
    const __nv_bfloat16* pAh = g_h_hi + hrow;
    const __nv_bfloat16* pAl = g_h_lo + hrow;
    __nv_bfloat16* dAh = sAh + arow * SA + ahalf * 16;
    __nv_bfloat16* dAl = sAl + arow * SA + ahalf * 16;

    int brow = tid >> 3, bq = tid & 7;
    const float* pB = wd + (size_t)e * D_FF * D_MODEL + (size_t)brow * D_MODEL + n0 + bq * 8;
    uint4* dBh = (uint4*)(sBh + brow * SB + bq * 8);
    uint4* dBl = (uint4*)(sBl + brow * SB + bq * 8);

    uint32_t bAh = smem_u32(sAh), bAl = smem_u32(sAl);
    uint32_t bBh = smem_u32(sBh), bBl = smem_u32(sBl);

    float ac[2][4][4];
#pragma unroll
    for (int i = 0; i < 2; i++)
#pragma unroll
        for (int j = 0; j < 4; j++)
#pragma unroll
            for (int q = 0; q < 4; q++) ac[i][j][q] = 0.0f;

    for (int c = 0; c < D_FF / 32; c++) {         // 64 chunks
        int k0 = c * 32;
        if (c > 0) __syncthreads();
        *(uint4*)dAh       = *(const uint4*)(pAh + k0);
        *(uint4*)(dAh + 8) = *(const uint4*)(pAh + k0 + 8);
        *(uint4*)dAl       = *(const uint4*)(pAl + k0);
        *(uint4*)(dAl + 8) = *(const uint4*)(pAl + k0 + 8);
        {
            const float* s = pB + (size_t)k0 * D_MODEL;
            float4 f0 = *(const float4*)s, f1 = *(const float4*)(s + 4);
            uint4 hi, lo; cvt8(f0, f1, hi, lo);
            *dBh = hi; *dBl = lo;
        }
        __syncthreads();

#pragma unroll
        for (int kk = 0; kk < 32; kk += 16) {
            uint32_t ah[2][4], al[2][4];
#pragma unroll
            for (int mf = 0; mf < 2; mf++) {
                uint32_t ro = wm * 32 + mf * 16 + (lane & 15);
                uint32_t co = kk + (lane >> 4) * 8;
                ldsm4(ah[mf], bAh + (ro * SA + co) * 2);
                ldsm4(al[mf], bAl + (ro * SA + co) * 2);
            }
            uint32_t kr = kk + (lane & 7) + ((lane >> 4) & 1) * 8;
            uint32_t ncol = wn * 32 + ((lane >> 3) & 1) * 8;
            uint32_t bh[4][2], bl[4][2], r4[4];
#pragma unroll
            for (int p = 0; p < 2; p++) {
                uint32_t off = (kr * SB + ncol + p * 16) * 2;
                ldsm4t(r4, bBh + off);
                bh[p*2][0] = r4[0]; bh[p*2+1][0] = r4[1]; bh[p*2][1] = r4[2]; bh[p*2+1][1] = r4[3];
                ldsm4t(r4, bBl + off);
                bl[p*2][0] = r4[0]; bl[p*2+1][0] = r4[1]; bl[p*2][1] = r4[2]; bl[p*2+1][1] = r4[3];
            }
#pragma unroll
            for (int mf = 0; mf < 2; mf++)
#pragma unroll
                for (int nf = 0; nf < 4; nf++) {
                    mma16816(ac[mf][nf], ah[mf], bh[nf][0], bh[nf][1]);
                    mma16816(ac[mf][nf], ah[mf], bl[nf][0], bl[nf][1]);
                    mma16816(ac[mf][nf], al[mf], bh[nf][0], bh[nf][1]);
                }
        }
    }

    // ---- epilogue: weighted atomic scatter-add ----
    int lr = lane >> 2, lc = (lane & 3) * 2;
#pragma unroll
    for (int mf = 0; mf < 2; mf++)
#pragma unroll
        for (int half = 0; half < 2; half++) {
            int slot = r0 + wm * 32 + mf * 16 + lr + half * 8;
            if (slot >= cnt) continue;
            int   tok = g_rows[e * CAP + slot];
            float w   = g_wts [e * CAP + slot];
            float* orow = out + (size_t)tok * D_MODEL + n0 + wn * 32 + lc;
#pragma unroll
            for (int nf = 0; nf < 4; nf++) {
                atomicAdd(&orow[nf * 8 + 0], ac[mf][nf][half * 2 + 0] * w);
                atomicAdd(&orow[nf * 8 + 1], ac[mf][nf][half * 2 + 1] * w);
            }
        }
}

// ======================= launch =======================
extern "C" void kernel_launch(void* const* d_in, const int* in_sizes, int n_in,
                              void* d_out, int out_size) {
    const float* x      = (const float*)d_in[0];   // [2,1024,768]
    const float* gate_w = (const float*)d_in[1];   // [768,8]
    const float* w_gate = (const float*)d_in[2];   // [8,768,2048]
    const float* w_up   = (const float*)d_in[3];   // [8,768,2048]
    const float* w_down = (const float*)d_in[4];   // [8,2048,768]
    float* out = (float*)d_out;

    k_reset<<<512, 256>>>(out, out_size);
    k_router<<<T_TOK / 8, 256>>>(x, gate_w);
    k_scatter<<<(T_TOK * 2 + 255) / 256, 256>>>();
    k_cvt_x<<<(T_TOK * D_MODEL / 4 + 255) / 256, 256>>>(x);

    {   // fused gate/up HMMA + SiLU
        dim3 grid(D_FF / 64, CAP / 128, NE);
        k_hmma_gu<<<grid, 256>>>(w_gate, w_up);
    }
    {   // down HMMA + weighted scatter-add
        dim3 grid(D_MODEL / 64, CAP / 128, NE);
        k_hmma_down<<<grid, 256>>>(w_down, out);
    }
}

// round 9
// speedup vs baseline: 1.1299x; 1.0421x over previous
#include <cuda_runtime.h>
#include <cuda_bf16.h>
#include <cstdint>
#include <math.h>

#define D_MODEL 768
#define D_FF    2048
#define NE      8
#define T_TOK   2048
#define CAP     2048

// ======================= scratch (__device__ globals) =======================
__device__ int   g_count[NE];
__device__ int   g_fill[NE];
__device__ int   g_rows[NE * CAP];
__device__ float g_wts [NE * CAP];
__device__ int   g_topi[T_TOK * 2];
__device__ float g_topw[T_TOK * 2];

__device__ __align__(16) __nv_bfloat16 g_xhi[T_TOK * D_MODEL];
__device__ __align__(16) __nv_bfloat16 g_xlo[T_TOK * D_MODEL];
// h = silu(g)*u, split hi/lo: [E][CAP][D_FF]
__device__ __align__(16) __nv_bfloat16 g_h_hi[(size_t)NE * CAP * D_FF];
__device__ __align__(16) __nv_bfloat16 g_h_lo[(size_t)NE * CAP * D_FF];

// ======================= helpers =======================
__device__ __forceinline__ uint32_t smem_u32(const void* p) {
    uint32_t a;
    asm("{ .reg .u64 t; cvta.to.shared.u64 t, %1; cvt.u32.u64 %0, t; }" : "=r"(a) : "l"(p));
    return a;
}
__device__ __forceinline__ void ldsm4(uint32_t (&r)[4], uint32_t addr) {
    asm volatile("ldmatrix.sync.aligned.m8n8.x4.shared.b16 {%0,%1,%2,%3}, [%4];"
                 : "=r"(r[0]), "=r"(r[1]), "=r"(r[2]), "=r"(r[3]) : "r"(addr));
}
__device__ __forceinline__ void ldsm4t(uint32_t (&r)[4], uint32_t addr) {
    asm volatile("ldmatrix.sync.aligned.m8n8.x4.trans.shared.b16 {%0,%1,%2,%3}, [%4];"
                 : "=r"(r[0]), "=r"(r[1]), "=r"(r[2]), "=r"(r[3]) : "r"(addr));
}
__device__ __forceinline__ void mma16816(float (&d)[4], const uint32_t (&a)[4],
                                         uint32_t b0, uint32_t b1) {
    asm volatile(
        "mma.sync.aligned.m16n8k16.row.col.f32.bf16.bf16.f32 "
        "{%0,%1,%2,%3}, {%4,%5,%6,%7}, {%8,%9}, {%0,%1,%2,%3};"
        : "+f"(d[0]), "+f"(d[1]), "+f"(d[2]), "+f"(d[3])
        : "r"(a[0]), "r"(a[1]), "r"(a[2]), "r"(a[3]), "r"(b0), "r"(b1));
}

__device__ __forceinline__ uint32_t pack2(__nv_bfloat16 a, __nv_bfloat16 b) {
    __nv_bfloat162 p = __halves2bfloat162(a, b);
    return *reinterpret_cast<uint32_t*>(&p);
}
// 8 fp32 -> 8 hi bf16 + 8 lo bf16 (packed as uint4 each)
__device__ __forceinline__ void cvt8(const float4& f0, const float4& f1,
                                     uint4& hi, uint4& lo) {
    float f[8] = {f0.x, f0.y, f0.z, f0.w, f1.x, f1.y, f1.z, f1.w};
    __nv_bfloat16 h[8], l[8];
#pragma unroll
    for (int i = 0; i < 8; i++) {
        h[i] = __float2bfloat16(f[i]);
        l[i] = __float2bfloat16(f[i] - __bfloat162float(h[i]));
    }
    hi = make_uint4(pack2(h[0], h[1]), pack2(h[2], h[3]), pack2(h[4], h[5]), pack2(h[6], h[7]));
    lo = make_uint4(pack2(l[0], l[1]), pack2(l[2], l[3]), pack2(l[4], l[5]), pack2(l[6], l[7]));
}

// ======================= small kernels =======================
__global__ void k_reset(float* __restrict__ out, int out_n) {
    int i = blockIdx.x * blockDim.x + threadIdx.x;
    if (i < NE) { g_count[i] = 0; g_fill[i] = 0; }
    for (int j = i; j < out_n; j += gridDim.x * blockDim.x) out[j] = 0.0f;
}

__global__ void k_router(const float* __restrict__ x, const float* __restrict__ gw) {
    int t = blockIdx.x * (blockDim.x >> 5) + (threadIdx.x >> 5);
    int lane = threadIdx.x & 31;
    if (t >= T_TOK) return;
    const float* xr = x + (size_t)t * D_MODEL;
    float acc[NE];
#pragma unroll
    for (int e = 0; e < NE; e++) acc[e] = 0.0f;
    for (int d = lane; d < D_MODEL; d += 32) {
        float xv = xr[d];
        const float* g = gw + (size_t)d * NE;
#pragma unroll
        for (int e = 0; e < NE; e++) acc[e] += xv * g[e];
    }
#pragma unroll
    for (int off = 16; off > 0; off >>= 1)
#pragma unroll
        for (int e = 0; e < NE; e++) acc[e] += __shfl_xor_sync(0xFFFFFFFFu, acc[e], off);

    if (lane == 0) {
        int i0 = 0;
#pragma unroll
        for (int e = 1; e < NE; e++) if (acc[e] > acc[i0]) i0 = e;
        int i1 = -1; float b = -1e30f;
#pragma unroll
        for (int e = 0; e < NE; e++) if (e != i0 && acc[e] > b) { b = acc[e]; i1 = e; }
        float w1 = expf(acc[i1] - acc[i0]);
        float s  = 1.0f + w1;
        g_topi[t * 2 + 0] = i0;  g_topw[t * 2 + 0] = 1.0f / s;
        g_topi[t * 2 + 1] = i1;  g_topw[t * 2 + 1] = w1 / s;
        atomicAdd(&g_count[i0], 1);
        atomicAdd(&g_count[i1], 1);
    }
}

__global__ void k_scatter() {
    int idx = blockIdx.x * blockDim.x + threadIdx.x;
    if (idx >= T_TOK * 2) return;
    int e = g_topi[idx];
    int p = atomicAdd(&g_fill[e], 1);
    g_rows[e * CAP + p] = idx >> 1;
    g_wts [e * CAP + p] = g_topw[idx];
}

// vectorized: 4 fp32 -> 4 hi + 4 lo bf16 per thread
__global__ void k_cvt_x(const float* __restrict__ x) {
    int i = blockIdx.x * blockDim.x + threadIdx.x;
    if (i >= T_TOK * D_MODEL / 4) return;
    float4 f = reinterpret_cast<const float4*>(x)[i];
    float v[4] = {f.x, f.y, f.z, f.w};
    __nv_bfloat16 h[4], l[4];
#pragma unroll
    for (int j = 0; j < 4; j++) {
        h[j] = __float2bfloat16(v[j]);
        l[j] = __float2bfloat16(v[j] - __bfloat162float(h[j]));
    }
    reinterpret_cast<uint2*>(g_xhi)[i] = make_uint2(pack2(h[0], h[1]), pack2(h[2], h[3]));
    reinterpret_cast<uint2*>(g_xlo)[i] = make_uint2(pack2(l[0], l[1]), pack2(l[2], l[3]));
}

// ======================= HMMA GEMM kernels =======================
// Tile: M=128 x N=64, K-chunk 64. 256 threads = 8 warps in 4(m) x 2(n).
// A smem row stride 72 bf16 (144B), B 72 bf16 (144B): odd x 16B -> ldmatrix conflict-free.
#define SA 72
#define SB 72
#define KCH 64

// dynamic smem offsets (bytes)
static constexpr int A_PREC  = 128 * SA * 2;          // 18432 per precision
static constexpr int B_PREC  = KCH * SB * 2;          // 9216 per precision
static constexpr int OFF_AH = 0;
static constexpr int OFF_AL = A_PREC;
static constexpr int OFF_GH = 2 * A_PREC;             // 36864
static constexpr int OFF_GL = OFF_GH + B_PREC;
static constexpr int OFF_UH = OFF_GL + B_PREC;
static constexpr int OFF_UL = OFF_UH + B_PREC;
static constexpr int SMEM_GU = OFF_UL + B_PREC;       // 73728
static constexpr int OFF_BH = 2 * A_PREC;
static constexpr int OFF_BL = OFF_BH + B_PREC;
static constexpr int SMEM_DN = OFF_BL + B_PREC;       // 55296

// h = silu(x@Wg) * (x@Wu)  (weights read fp32 [k][n] native layout, converted inline)
__global__ void __launch_bounds__(256) k_hmma_gu(
    const float* __restrict__ wg, const float* __restrict__ wu)
{
    int e   = blockIdx.z;
    int cnt = g_count[e];
    int r0  = blockIdx.y * 128;
    if (r0 >= cnt) return;
    int n0  = blockIdx.x * 64;

    extern __shared__ char smem[];
    uint32_t sb = smem_u32(smem);

    int tid = threadIdx.x, lane = tid & 31, wid = tid >> 5;
    int wm = wid >> 1, wn = wid & 1;

    // --- A loader: 2 threads/row, 32 cols each ---
    int arow = tid >> 1, aq = tid & 1;
    int slotA = r0 + arow;
    int tok = (slotA < cnt) ? g_rows[e * CAP + slotA] : 0;
    const __nv_bfloat16* pAh = g_xhi + (size_t)tok * D_MODEL + aq * 32;
    const __nv_bfloat16* pAl = g_xlo + (size_t)tok * D_MODEL + aq * 32;
    __nv_bfloat16* dAh = (__nv_bfloat16*)(smem + OFF_AH) + arow * SA + aq * 32;
    __nv_bfloat16* dAl = (__nv_bfloat16*)(smem + OFF_AL) + arow * SA + aq * 32;

    // --- B loader: 4 threads/row, 16 cols each, 64 k-rows ---
    int brow = tid >> 2, bq = tid & 3;
    const float* pG = wg + (size_t)e * D_MODEL * D_FF + (size_t)brow * D_FF + n0 + bq * 16;
    const float* pU = wu + (size_t)e * D_MODEL * D_FF + (size_t)brow * D_FF + n0 + bq * 16;
    __nv_bfloat16* dGh = (__nv_bfloat16*)(smem + OFF_GH) + brow * SB + bq * 16;
    __nv_bfloat16* dGl = (__nv_bfloat16*)(smem + OFF_GL) + brow * SB + bq * 16;
    __nv_bfloat16* dUh = (__nv_bfloat16*)(smem + OFF_UH) + brow * SB + bq * 16;
    __nv_bfloat16* dUl = (__nv_bfloat16*)(smem + OFF_UL) + brow * SB + bq * 16;

    uint32_t bAh = sb + OFF_AH, bAl = sb + OFF_AL;
    uint32_t bGh = sb + OFF_GH, bGl = sb + OFF_GL;
    uint32_t bUh = sb + OFF_UH, bUl = sb + OFF_UL;

    float ag[2][4][4], au[2][4][4];
#pragma unroll
    for (int i = 0; i < 2; i++)
#pragma unroll
        for (int j = 0; j < 4; j++)
#pragma unroll
            for (int q = 0; q < 4; q++) { ag[i][j][q] = 0.0f; au[i][j][q] = 0.0f; }

    for (int c = 0; c < D_MODEL / KCH; c++) {     // 12 chunks
        int k0 = c * KCH;
        if (c > 0) __syncthreads();
        // A fill: 32 bf16 per thread per precision (4 uint4, batched loads)
        {
            uint4 v0 = *(const uint4*)(pAh + k0);
            uint4 v1 = *(const uint4*)(pAh + k0 + 8);
            uint4 v2 = *(const uint4*)(pAh + k0 + 16);
            uint4 v3 = *(const uint4*)(pAh + k0 + 24);
            *(uint4*)(dAh)      = v0; *(uint4*)(dAh + 8)  = v1;
            *(uint4*)(dAh + 16) = v2; *(uint4*)(dAh + 24) = v3;
            v0 = *(const uint4*)(pAl + k0);
            v1 = *(const uint4*)(pAl + k0 + 8);
            v2 = *(const uint4*)(pAl + k0 + 16);
            v3 = *(const uint4*)(pAl + k0 + 24);
            *(uint4*)(dAl)      = v0; *(uint4*)(dAl + 8)  = v1;
            *(uint4*)(dAl + 16) = v2; *(uint4*)(dAl + 24) = v3;
        }
        // B fill: 16 fp32 -> hi/lo per matrix
        {
            const float* s = pG + (size_t)k0 * D_FF;
            float4 f0 = *(const float4*)s,       f1 = *(const float4*)(s + 4);
            float4 f2 = *(const float4*)(s + 8), f3 = *(const float4*)(s + 12);
            uint4 hi, lo;
            cvt8(f0, f1, hi, lo); *(uint4*)dGh = hi;       *(uint4*)dGl = lo;
            cvt8(f2, f3, hi, lo); *(uint4*)(dGh + 8) = hi; *(uint4*)(dGl + 8) = lo;
        }
        {
            const float* s = pU + (size_t)k0 * D_FF;
            float4 f0 = *(const float4*)s,       f1 = *(const float4*)(s + 4);
            float4 f2 = *(const float4*)(s + 8), f3 = *(const float4*)(s + 12);
            uint4 hi, lo;
            cvt8(f0, f1, hi, lo); *(uint4*)dUh = hi;       *(uint4*)dUl = lo;
            cvt8(f2, f3, hi, lo); *(uint4*)(dUh + 8) = hi; *(uint4*)(dUl + 8) = lo;
        }
        __syncthreads();

#pragma unroll
        for (int kk = 0; kk < KCH; kk += 16) {
            uint32_t ah[2][4], al[2][4];
#pragma unroll
            for (int mf = 0; mf < 2; mf++) {
                uint32_t ro = wm * 32 + mf * 16 + (lane & 15);
                uint32_t co = kk + (lane >> 4) * 8;
                ldsm4(ah[mf], bAh + (ro * SA + co) * 2);
                ldsm4(al[mf], bAl + (ro * SA + co) * 2);
            }
            uint32_t kr = kk + (lane & 7) + ((lane >> 4) & 1) * 8;
            uint32_t ncol = wn * 32 + ((lane >> 3) & 1) * 8;
            // ---- gate ----
            {
                uint32_t bh[4][2], bl[4][2], r4[4];
#pragma unroll
                for (int p = 0; p < 2; p++) {
                    uint32_t off = (kr * SB + ncol + p * 16) * 2;
                    ldsm4t(r4, bGh + off);
                    bh[p*2][0] = r4[0]; bh[p*2+1][0] = r4[1]; bh[p*2][1] = r4[2]; bh[p*2+1][1] = r4[3];
                    ldsm4t(r4, bGl + off);
                    bl[p*2][0] = r4[0]; bl[p*2+1][0] = r4[1]; bl[p*2][1] = r4[2]; bl[p*2+1][1] = r4[3];
                }
#pragma unroll
                for (int mf = 0; mf < 2; mf++)
#pragma unroll
                    for (int nf = 0; nf < 4; nf++) {
                        mma16816(ag[mf][nf], ah[mf], bh[nf][0], bh[nf][1]);
                        mma16816(ag[mf][nf], ah[mf], bl[nf][0], bl[nf][1]);
                        mma16816(ag[mf][nf], al[mf], bh[nf][0], bh[nf][1]);
                    }
            }
            // ---- up ----
            {
                uint32_t bh[4][2], bl[4][2], r4[4];
#pragma unroll
                for (int p = 0; p < 2; p++) {
                    uint32_t off = (kr * SB + ncol + p * 16) * 2;
                    ldsm4t(r4, bUh + off);
                    bh[p*2][0] = r4[0]; bh[p*2+1][0] = r4[1]; bh[p*2][1] = r4[2]; bh[p*2+1][1] = r4[3];
                    ldsm4t(r4, bUl + off);
                    bl[p*2][0] = r4[0]; bl[p*2+1][0] = r4[1]; bl[p*2][1] = r4[2]; bl[p*2+1][1] = r4[3];
                }
#pragma unroll
                for (int mf = 0; mf < 2; mf++)
#pragma unroll
                    for (int nf = 0; nf < 4; nf++) {
                        mma16816(au[mf][nf], ah[mf], bh[nf][0], bh[nf][1]);
                        mma16816(au[mf][nf], ah[mf], bl[nf][0], bl[nf][1]);
                        mma16816(au[mf][nf], al[mf], bh[nf][0], bh[nf][1]);
                    }
            }
        }
    }

    // ---- epilogue: h = silu(g)*u -> split bf16 ----
    int lr = lane >> 2, lc = (lane & 3) * 2;
#pragma unroll
    for (int mf = 0; mf < 2; mf++)
#pragma unroll
        for (int half = 0; half < 2; half++) {
            int slot = r0 + wm * 32 + mf * 16 + lr + half * 8;
            if (slot >= cnt) continue;
            size_t base = ((size_t)e * CAP + slot) * D_FF + n0 + wn * 32 + lc;
#pragma unroll
            for (int nf = 0; nf < 4; nf++) {
                float g0 = ag[mf][nf][half * 2 + 0], g1 = ag[mf][nf][half * 2 + 1];
                float u0 = au[mf][nf][half * 2 + 0], u1 = au[mf][nf][half * 2 + 1];
                float h0 = (g0 / (1.0f + __expf(-g0))) * u0;
                float h1 = (g1 / (1.0f + __expf(-g1))) * u1;
                __nv_bfloat16 h0h = __float2bfloat16(h0);
                __nv_bfloat16 h1h = __float2bfloat16(h1);
                __nv_bfloat16 h0l = __float2bfloat16(h0 - __bfloat162float(h0h));
                __nv_bfloat16 h1l = __float2bfloat16(h1 - __bfloat162float(h1h));
                *(__nv_bfloat162*)(g_h_hi + base + nf * 8) = __halves2bfloat162(h0h, h1h);
                *(__nv_bfloat162*)(g_h_lo + base + nf * 8) = __halves2bfloat162(h0l, h1l);
            }
        }
}

// out[token] += gate_wt * (h @ Wd)
__global__ void __launch_bounds__(256) k_hmma_down(
    const float* __restrict__ wd, float* __restrict__ out)
{
    int e   = blockIdx.z;
    int cnt = g_count[e];
    int r0  = blockIdx.y * 128;
    if (r0 >= cnt) return;
    int n0  = blockIdx.x * 64;

    extern __shared__ char smem[];
    uint32_t sb = smem_u32(smem);

    int tid = threadIdx.x, lane = tid & 31, wid = tid >> 5;
    int wm = wid >> 1, wn = wid & 1;

    int arow = tid >> 1, aq = tid & 1;
    int slotA = r0 + arow;
    int asafe = (slotA < cnt) ? slotA : 0;
    size_t hrow = ((size_t)e * CAP + asafe) * D_FF + aq * 32;
    const __nv_bfloat16* pAh = g_h_hi + hrow;
    const __nv_bfloat16* pAl = g_h_lo + hrow;
    __nv_bfloat16* dAh = (__nv_bfloat16*)(smem + OFF_AH) + arow * SA + aq * 32;
    __nv_bfloat16* dAl = (__nv_bfloat16*)(smem + OFF_AL) + arow * SA + aq * 32;

    int brow = tid >> 2, bq = tid & 3;
    const float* pB = wd + (size_t)e * D_FF * D_MODEL + (size_t)brow * D_MODEL + n0 + bq * 16;
    __nv_bfloat16* dBh = (__nv_bfloat16*)(smem + OFF_BH) + brow * SB + bq * 16;
    __nv_bfloat16* dBl = (__nv_bfloat16*)(smem + OFF_BL) + brow * SB + bq * 16;

    uint32_t bAh = sb + OFF_AH, bAl = sb + OFF_AL;
    uint32_t bBh = sb + OFF_BH, bBl = sb + OFF_BL;

    float ac[2][4][4];
#pragma unroll
    for (int i = 0; i < 2; i++)
#pragma unroll
        for (int j = 0; j < 4; j++)
#pragma unroll
            for (int q = 0; q < 4; q++) ac[i][j][q] = 0.0f;

    for (int c = 0; c < D_FF / KCH; c++) {        // 32 chunks
        int k0 = c * KCH;
        if (c > 0) __syncthreads();
        {
            uint4 v0 = *(const uint4*)(pAh + k0);
            uint4 v1 = *(const uint4*)(pAh + k0 + 8);
            uint4 v2 = *(const uint4*)(pAh + k0 + 16);
            uint4 v3 = *(const uint4*)(pAh + k0 + 24);
            *(uint4*)(dAh)      = v0; *(uint4*)(dAh + 8)  = v1;
            *(uint4*)(dAh + 16) = v2; *(uint4*)(dAh + 24) = v3;
            v0 = *(const uint4*)(pAl + k0);
            v1 = *(const uint4*)(pAl + k0 + 8);
            v2 = *(const uint4*)(pAl + k0 + 16);
            v3 = *(const uint4*)(pAl + k0 + 24);
            *(uint4*)(dAl)      = v0; *(uint4*)(dAl + 8)  = v1;
            *(uint4*)(dAl + 16) = v2; *(uint4*)(dAl + 24) = v3;
        }
        {
            const float* s = pB + (size_t)k0 * D_MODEL;
            float4 f0 = *(const float4*)s,       f1 = *(const float4*)(s + 4);
            float4 f2 = *(const float4*)(s + 8), f3 = *(const float4*)(s + 12);
            uint4 hi, lo;
            cvt8(f0, f1, hi, lo); *(uint4*)dBh = hi;       *(uint4*)dBl = lo;
            cvt8(f2, f3, hi, lo); *(uint4*)(dBh + 8) = hi; *(uint4*)(dBl + 8) = lo;
        }
        __syncthreads();

#pragma unroll
        for (int kk = 0; kk < KCH; kk += 16) {
            uint32_t ah[2][4], al[2][4];
#pragma unroll
            for (int mf = 0; mf < 2; mf++) {
                uint32_t ro = wm * 32 + mf * 16 + (lane & 15);
                uint32_t co = kk + (lane >> 4) * 8;
                ldsm4(ah[mf], bAh + (ro * SA + co) * 2);
                ldsm4(al[mf], bAl + (ro * SA + co) * 2);
            }
            uint32_t kr = kk + (lane & 7) + ((lane >> 4) & 1) * 8;
            uint32_t ncol = wn * 32 + ((lane >> 3) & 1) * 8;
            uint32_t bh[4][2], bl[4][2], r4[4];
#pragma unroll
            for (int p = 0; p < 2; p++) {
                uint32_t off = (kr * SB + ncol + p * 16) * 2;
                ldsm4t(r4, bBh + off);
                bh[p*2][0] = r4[0]; bh[p*2+1][0] = r4[1]; bh[p*2][1] = r4[2]; bh[p*2+1][1] = r4[3];
                ldsm4t(r4, bBl + off);
                bl[p*2][0] = r4[0]; bl[p*2+1][0] = r4[1]; bl[p*2][1] = r4[2]; bl[p*2+1][1] = r4[3];
            }
#pragma unroll
            for (int mf = 0; mf < 2; mf++)
#pragma unroll
                for (int nf = 0; nf < 4; nf++) {
                    mma16816(ac[mf][nf], ah[mf], bh[nf][0], bh[nf][1]);
                    mma16816(ac[mf][nf], ah[mf], bl[nf][0], bl[nf][1]);
                    mma16816(ac[mf][nf], al[mf], bh[nf][0], bh[nf][1]);
                }
        }
    }

    // ---- epilogue: weighted atomic scatter-add ----
    int lr = lane >> 2, lc = (lane & 3) * 2;
#pragma unroll
    for (int mf = 0; mf < 2; mf++)
#pragma unroll
        for (int half = 0; half < 2; half++) {
            int slot = r0 + wm * 32 + mf * 16 + lr + half * 8;
            if (slot >= cnt) continue;
            int   tok = g_rows[e * CAP + slot];
            float w   = g_wts [e * CAP + slot];
            float* orow = out + (size_t)tok * D_MODEL + n0 + wn * 32 + lc;
#pragma unroll
            for (int nf = 0; nf < 4; nf++) {
                atomicAdd(&orow[nf * 8 + 0], ac[mf][nf][half * 2 + 0] * w);
                atomicAdd(&orow[nf * 8 + 1], ac[mf][nf][half * 2 + 1] * w);
            }
        }
}

// ======================= launch =======================
extern "C" void kernel_launch(void* const* d_in, const int* in_sizes, int n_in,
                              void* d_out, int out_size) {
    const float* x      = (const float*)d_in[0];   // [2,1024,768]
    const float* gate_w = (const float*)d_in[1];   // [768,8]
    const float* w_gate = (const float*)d_in[2];   // [8,768,2048]
    const float* w_up   = (const float*)d_in[3];   // [8,768,2048]
    const float* w_down = (const float*)d_in[4];   // [8,2048,768]
    float* out = (float*)d_out;

    cudaFuncSetAttribute(k_hmma_gu,   cudaFuncAttributeMaxDynamicSharedMemorySize, SMEM_GU);
    cudaFuncSetAttribute(k_hmma_down, cudaFuncAttributeMaxDynamicSharedMemorySize, SMEM_DN);

    k_reset<<<512, 256>>>(out, out_size);
    k_router<<<T_TOK / 8, 256>>>(x, gate_w);
    k_scatter<<<(T_TOK * 2 + 255) / 256, 256>>>();
    k_cvt_x<<<(T_TOK * D_MODEL / 4 + 255) / 256, 256>>>(x);

    {   // fused gate/up HMMA + SiLU
        dim3 grid(D_FF / 64, CAP / 128, NE);
        k_hmma_gu<<<grid, 256, SMEM_GU>>>(w_gate, w_up);
    }
    {   // down HMMA + weighted scatter-add
        dim3 grid(D_MODEL / 64, CAP / 128, NE);
        k_hmma_down<<<grid, 256, SMEM_DN>>>(w_down, out);
    }
}

// round 10
// speedup vs baseline: 1.3446x; 1.1900x over previous
#include <cuda_runtime.h>
#include <cuda_fp16.h>
#include <cstdint>
#include <math.h>

#define D_MODEL 768
#define D_FF    2048
#define NE      8
#define T_TOK   2048
#define CAP     2048

// ======================= scratch (__device__ globals) =======================
__device__ int   g_count[NE];
__device__ int   g_fill[NE];
__device__ int   g_rows[NE * CAP];
__device__ float g_wts [NE * CAP];
__device__ int   g_topi[T_TOK * 2];
__device__ float g_topw[T_TOK * 2];

__device__ __align__(16) __half g_xhi[T_TOK * D_MODEL];
__device__ __align__(16) __half g_xlo[T_TOK * D_MODEL];
// h = silu(g)*u, split hi/lo fp16: [E][CAP][D_FF]
__device__ __align__(16) __half g_h_hi[(size_t)NE * CAP * D_FF];
__device__ __align__(16) __half g_h_lo[(size_t)NE * CAP * D_FF];

// ======================= helpers =======================
__device__ __forceinline__ uint32_t smem_u32(const void* p) {
    uint32_t a;
    asm("{ .reg .u64 t; cvta.to.shared.u64 t, %1; cvt.u32.u64 %0, t; }" : "=r"(a) : "l"(p));
    return a;
}
__device__ __forceinline__ void ldsm4(uint32_t (&r)[4], uint32_t addr) {
    asm volatile("ldmatrix.sync.aligned.m8n8.x4.shared.b16 {%0,%1,%2,%3}, [%4];"
                 : "=r"(r[0]), "=r"(r[1]), "=r"(r[2]), "=r"(r[3]) : "r"(addr));
}
__device__ __forceinline__ void ldsm4t(uint32_t (&r)[4], uint32_t addr) {
    asm volatile("ldmatrix.sync.aligned.m8n8.x4.trans.shared.b16 {%0,%1,%2,%3}, [%4];"
                 : "=r"(r[0]), "=r"(r[1]), "=r"(r[2]), "=r"(r[3]) : "r"(addr));
}
// fp16 inputs, fp32 accumulate
__device__ __forceinline__ void mma16816(float (&d)[4], const uint32_t (&a)[4],
                                         uint32_t b0, uint32_t b1) {
    asm volatile(
        "mma.sync.aligned.m16n8k16.row.col.f32.f16.f16.f32 "
        "{%0,%1,%2,%3}, {%4,%5,%6,%7}, {%8,%9}, {%0,%1,%2,%3};"
        : "+f"(d[0]), "+f"(d[1]), "+f"(d[2]), "+f"(d[3])
        : "r"(a[0]), "r"(a[1]), "r"(a[2]), "r"(a[3]), "r"(b0), "r"(b1));
}

__device__ __forceinline__ uint32_t pack2h(__half a, __half b) {
    __half2 p = __halves2half2(a, b);
    return *reinterpret_cast<uint32_t*>(&p);
}
// 8 fp32 -> 8 fp16 (hi only), packed as uint4
__device__ __forceinline__ uint4 cvt8h(const float4& f0, const float4& f1) {
    return make_uint4(
        pack2h(__float2half_rn(f0.x), __float2half_rn(f0.y)),
        pack2h(__float2half_rn(f0.z), __float2half_rn(f0.w)),
        pack2h(__float2half_rn(f1.x), __float2half_rn(f1.y)),
        pack2h(__float2half_rn(f1.z), __float2half_rn(f1.w)));
}

// ======================= small kernels =======================
__global__ void k_reset(float* __restrict__ out, int out_n) {
    int i = blockIdx.x * blockDim.x + threadIdx.x;
    if (i < NE) { g_count[i] = 0; g_fill[i] = 0; }
    for (int j = i; j < out_n; j += gridDim.x * blockDim.x) out[j] = 0.0f;
}

__global__ void k_router(const float* __restrict__ x, const float* __restrict__ gw) {
    int t = blockIdx.x * (blockDim.x >> 5) + (threadIdx.x >> 5);
    int lane = threadIdx.x & 31;
    if (t >= T_TOK) return;
    const float* xr = x + (size_t)t * D_MODEL;
    float acc[NE];
#pragma unroll
    for (int e = 0; e < NE; e++) acc[e] = 0.0f;
    for (int d = lane; d < D_MODEL; d += 32) {
        float xv = xr[d];
        const float* g = gw + (size_t)d * NE;
#pragma unroll
        for (int e = 0; e < NE; e++) acc[e] += xv * g[e];
    }
#pragma unroll
    for (int off = 16; off > 0; off >>= 1)
#pragma unroll
        for (int e = 0; e < NE; e++) acc[e] += __shfl_xor_sync(0xFFFFFFFFu, acc[e], off);

    if (lane == 0) {
        int i0 = 0;
#pragma unroll
        for (int e = 1; e < NE; e++) if (acc[e] > acc[i0]) i0 = e;
        int i1 = -1; float b = -1e30f;
#pragma unroll
        for (int e = 0; e < NE; e++) if (e != i0 && acc[e] > b) { b = acc[e]; i1 = e; }
        float w1 = expf(acc[i1] - acc[i0]);
        float s  = 1.0f + w1;
        g_topi[t * 2 + 0] = i0;  g_topw[t * 2 + 0] = 1.0f / s;
        g_topi[t * 2 + 1] = i1;  g_topw[t * 2 + 1] = w1 / s;
        atomicAdd(&g_count[i0], 1);
        atomicAdd(&g_count[i1], 1);
    }
}

__global__ void k_scatter() {
    int idx = blockIdx.x * blockDim.x + threadIdx.x;
    if (idx >= T_TOK * 2) return;
    int e = g_topi[idx];
    int p = atomicAdd(&g_fill[e], 1);
    g_rows[e * CAP + p] = idx >> 1;
    g_wts [e * CAP + p] = g_topw[idx];
}

// vectorized: 4 fp32 -> 4 hi + 4 lo fp16 per thread
__global__ void k_cvt_x(const float* __restrict__ x) {
    int i = blockIdx.x * blockDim.x + threadIdx.x;
    if (i >= T_TOK * D_MODEL / 4) return;
    float4 f = reinterpret_cast<const float4*>(x)[i];
    float v[4] = {f.x, f.y, f.z, f.w};
    __half h[4], l[4];
#pragma unroll
    for (int j = 0; j < 4; j++) {
        h[j] = __float2half_rn(v[j]);
        l[j] = __float2half_rn(v[j] - __half2float(h[j]));
    }
    reinterpret_cast<uint2*>(g_xhi)[i] = make_uint2(pack2h(h[0], h[1]), pack2h(h[2], h[3]));
    reinterpret_cast<uint2*>(g_xlo)[i] = make_uint2(pack2h(l[0], l[1]), pack2h(l[2], l[3]));
}

// ======================= HMMA GEMM kernels =======================
// Tile: M=128 x N=64, K-chunk 32. 256 threads = 8 warps in 4(m) x 2(n).
// A smem row stride 40 fp16 (80B), B 72 fp16 (144B) -> ldmatrix conflict-free.
#define SA 40
#define SB 72

// h = silu(x@Wg) * (x@Wu)  (weights read fp32 [k][n] native layout, converted inline)
__global__ void __launch_bounds__(256) k_hmma_gu(
    const float* __restrict__ wg, const float* __restrict__ wu)
{
    int e   = blockIdx.z;
    int cnt = g_count[e];
    int r0  = blockIdx.y * 128;
    if (r0 >= cnt) return;
    int n0  = blockIdx.x * 64;

    __shared__ __half sAh[128 * SA], sAl[128 * SA];
    __shared__ __half sGh[32 * SB];
    __shared__ __half sUh[32 * SB];

    int tid = threadIdx.x, lane = tid & 31, wid = tid >> 5;
    int wm = wid >> 1, wn = wid & 1;

    // --- loader setup ---
    int arow = tid >> 1, ahalf = tid & 1;
    int slotA = r0 + arow;
    int tok = (slotA < cnt) ? g_rows[e * CAP + slotA] : 0;
    const __half* pAh = g_xhi + (size_t)tok * D_MODEL + ahalf * 16;
    const __half* pAl = g_xlo + (size_t)tok * D_MODEL + ahalf * 16;
    __half* dAh = sAh + arow * SA + ahalf * 16;
    __half* dAl = sAl + arow * SA + ahalf * 16;

    int brow = tid >> 3, bq = tid & 7;      // 32 k-rows x 8 col-quads
    const float* pG = wg + (size_t)e * D_MODEL * D_FF + (size_t)brow * D_FF + n0 + bq * 8;
    const float* pU = wu + (size_t)e * D_MODEL * D_FF + (size_t)brow * D_FF + n0 + bq * 8;
    uint4* dGh = (uint4*)(sGh + brow * SB + bq * 8);
    uint4* dUh = (uint4*)(sUh + brow * SB + bq * 8);

    uint32_t bAh = smem_u32(sAh), bAl = smem_u32(sAl);
    uint32_t bGh = smem_u32(sGh);
    uint32_t bUh = smem_u32(sUh);

    float ag[2][4][4], au[2][4][4];
#pragma unroll
    for (int i = 0; i < 2; i++)
#pragma unroll
        for (int j = 0; j < 4; j++)
#pragma unroll
            for (int q = 0; q < 4; q++) { ag[i][j][q] = 0.0f; au[i][j][q] = 0.0f; }

    for (int c = 0; c < D_MODEL / 32; c++) {      // 24 chunks
        int k0 = c * 32;
        if (c > 0) __syncthreads();
        // A fill: 16 fp16 per thread per precision
        *(uint4*)dAh       = *(const uint4*)(pAh + k0);
        *(uint4*)(dAh + 8) = *(const uint4*)(pAh + k0 + 8);
        *(uint4*)dAl       = *(const uint4*)(pAl + k0);
        *(uint4*)(dAl + 8) = *(const uint4*)(pAl + k0 + 8);
        // B fill: 8 fp32 -> fp16 per matrix
        {
            const float* s = pG + (size_t)k0 * D_FF;
            float4 f0 = *(const float4*)s, f1 = *(const float4*)(s + 4);
            *dGh = cvt8h(f0, f1);
        }
        {
            const float* s = pU + (size_t)k0 * D_FF;
            float4 f0 = *(const float4*)s, f1 = *(const float4*)(s + 4);
            *dUh = cvt8h(f0, f1);
        }
        __syncthreads();

#pragma unroll
        for (int kk = 0; kk < 32; kk += 16) {
            uint32_t ah[2][4], al[2][4];
#pragma unroll
            for (int mf = 0; mf < 2; mf++) {
                uint32_t ro = wm * 32 + mf * 16 + (lane & 15);
                uint32_t co = kk + (lane >> 4) * 8;
                ldsm4(ah[mf], bAh + (ro * SA + co) * 2);
                ldsm4(al[mf], bAl + (ro * SA + co) * 2);
            }
            uint32_t kr = kk + (lane & 7) + ((lane >> 4) & 1) * 8;
            uint32_t ncol = wn * 32 + ((lane >> 3) & 1) * 8;
            // ---- gate ----
            {
                uint32_t bh[4][2], r4[4];
#pragma unroll
                for (int p = 0; p < 2; p++) {
                    uint32_t off = (kr * SB + ncol + p * 16) * 2;
                    ldsm4t(r4, bGh + off);
                    bh[p*2][0] = r4[0]; bh[p*2+1][0] = r4[1]; bh[p*2][1] = r4[2]; bh[p*2+1][1] = r4[3];
                }
#pragma unroll
                for (int mf = 0; mf < 2; mf++)
#pragma unroll
                    for (int nf = 0; nf < 4; nf++) {
                        mma16816(ag[mf][nf], ah[mf], bh[nf][0], bh[nf][1]);
                        mma16816(ag[mf][nf], al[mf], bh[nf][0], bh[nf][1]);
                    }
            }
            // ---- up ----
            {
                uint32_t bh[4][2], r4[4];
#pragma unroll
                for (int p = 0; p < 2; p++) {
                    uint32_t off = (kr * SB + ncol + p * 16) * 2;
                    ldsm4t(r4, bUh + off);
                    bh[p*2][0] = r4[0]; bh[p*2+1][0] = r4[1]; bh[p*2][1] = r4[2]; bh[p*2+1][1] = r4[3];
                }
#pragma unroll
                for (int mf = 0; mf < 2; mf++)
#pragma unroll
                    for (int nf = 0; nf < 4; nf++) {
                        mma16816(au[mf][nf], ah[mf], bh[nf][0], bh[nf][1]);
                        mma16816(au[mf][nf], al[mf], bh[nf][0], bh[nf][1]);
                    }
            }
        }
    }

    // ---- epilogue: h = silu(g)*u -> split fp16 ----
    int lr = lane >> 2, lc = (lane & 3) * 2;
#pragma unroll
    for (int mf = 0; mf < 2; mf++)
#pragma unroll
        for (int half = 0; half < 2; half++) {
            int slot = r0 + wm * 32 + mf * 16 + lr + half * 8;
            if (slot >= cnt) continue;
            size_t base = ((size_t)e * CAP + slot) * D_FF + n0 + wn * 32 + lc;
#pragma unroll
            for (int nf = 0; nf < 4; nf++) {
                float g0 = ag[mf][nf][half * 2 + 0], g1 = ag[mf][nf][half * 2 + 1];
                float u0 = au[mf][nf][half * 2 + 0], u1 = au[mf][nf][half * 2 + 1];
                float h0 = (g0 / (1.0f + __expf(-g0))) * u0;
                float h1 = (g1 / (1.0f + __expf(-g1))) * u1;
                __half h0h = __float2half_rn(h0);
                __half h1h = __float2half_rn(h1);
                __half h0l = __float2half_rn(h0 - __half2float(h0h));
                __half h1l = __float2half_rn(h1 - __half2float(h1h));
                *(__half2*)(g_h_hi + base + nf * 8) = __halves2half2(h0h, h1h);
                *(__half2*)(g_h_lo + base + nf * 8) = __halves2half2(h0l, h1l);
            }
        }
}

// out[token] += gate_wt * (h @ Wd)
__global__ void __launch_bounds__(256) k_hmma_down(
    const float* __restrict__ wd, float* __restrict__ out)
{
    int e   = blockIdx.z;
    int cnt = g_count[e];
    int r0  = blockIdx.y * 128;
    if (r0 >= cnt) return;
    int n0  = blockIdx.x * 64;

    __shared__ __half sAh[128 * SA], sAl[128 * SA];
    __shared__ __half sBh[32 * SB];

    int tid = threadIdx.x, lane = tid & 31, wid = tid >> 5;
    int wm = wid >> 1, wn = wid & 1;

    int arow = tid >> 1, ahalf = tid & 1;
    int slotA = r0 + arow;
    int asafe = (slotA < cnt) ? slotA : 0;
    size_t hrow = ((size_t)e * CAP + asafe) * D_FF + ahalf * 16;
    const __half* pAh = g_h_hi + hrow;
    const __half* pAl = g_h_lo + hrow;
    __half* dAh = sAh + arow * SA + ahalf * 16;
    __half* dAl = sAl + arow * SA + ahalf * 16;

    int brow = tid >> 3, bq = tid & 7;
    const float* pB = wd + (size_t)e * D_FF * D_MODEL + (size_t)brow * D_MODEL + n0 + bq * 8;
    uint4* dBh = (uint4*)(sBh + brow * SB + bq * 8);

    uint32_t bAh = smem_u32(sAh), bAl = smem_u32(sAl);
    uint32_t bBh = smem_u32(sBh);

    float ac[2][4][4];
#pragma unroll
    for (int i = 0; i < 2; i++)
#pragma unroll
        for (int j = 0; j < 4; j++)
#pragma unroll
            for (int q = 0; q < 4; q++) ac[i][j][q] = 0.0f;

    for (int c = 0; c < D_FF / 32; c++) {         // 64 chunks
        int k0 = c * 32;
        if (c > 0) __syncthreads();
        *(uint4*)dAh       = *(const uint4*)(pAh + k0);
        *(uint4*)(dAh + 8) = *(const uint4*)(pAh + k0 + 8);
        *(uint4*)dAl       = *(const uint4*)(pAl + k0);
        *(uint4*)(dAl + 8) = *(const uint4*)(pAl + k0 + 8);
        {
            const float* s = pB + (size_t)k0 * D_MODEL;
            float4 f0 = *(const float4*)s, f1 = *(const float4*)(s + 4);
            *dBh = cvt8h(f0, f1);
        }
        __syncthreads();

#pragma unroll
        for (int kk = 0; kk < 32; kk += 16) {
            uint32_t ah[2][4], al[2][4];
#pragma unroll
            for (int mf = 0; mf < 2; mf++) {
                uint32_t ro = wm * 32 + mf * 16 + (lane & 15);
                uint32_t co = kk + (lane >> 4) * 8;
                ldsm4(ah[mf], bAh + (ro * SA + co) * 2);
                ldsm4(al[mf], bAl + (ro * SA + co) * 2);
            }
            uint32_t kr = kk + (lane & 7) + ((lane >> 4) & 1) * 8;
            uint32_t ncol = wn * 32 + ((lane >> 3) & 1) * 8;
            uint32_t bh[4][2], r4[4];
#pragma unroll
            for (int p = 0; p < 2; p++) {
                uint32_t off = (kr * SB + ncol + p * 16) * 2;
                ldsm4t(r4, bBh + off);
                bh[p*2][0] = r4[0]; bh[p*2+1][0] = r4[1]; bh[p*2][1] = r4[2]; bh[p*2+1][1] = r4[3];
            }
#pragma unroll
            for (int mf = 0; mf < 2; mf++)
#pragma unroll
                for (int nf = 0; nf < 4; nf++) {
                    mma16816(ac[mf][nf], ah[mf], bh[nf][0], bh[nf][1]);
                    mma16816(ac[mf][nf], al[mf], bh[nf][0], bh[nf][1]);
                }
        }
    }

    // ---- epilogue: weighted atomic scatter-add ----
    int lr = lane >> 2, lc = (lane & 3) * 2;
#pragma unroll
    for (int mf = 0; mf < 2; mf++)
#pragma unroll
        for (int half = 0; half < 2; half++) {
            int slot = r0 + wm * 32 + mf * 16 + lr + half * 8;
            if (slot >= cnt) continue;
            int   tok = g_rows[e * CAP + slot];
            float w   = g_wts [e * CAP + slot];
            float* orow = out + (size_t)tok * D_MODEL + n0 + wn * 32 + lc;
#pragma unroll
            for (int nf = 0; nf < 4; nf++) {
                atomicAdd(&orow[nf * 8 + 0], ac[mf][nf][half * 2 + 0] * w);
                atomicAdd(&orow[nf * 8 + 1], ac[mf][nf][half * 2 + 1] * w);
            }
        }
}

// ======================= launch =======================
extern "C" void kernel_launch(void* const* d_in, const int* in_sizes, int n_in,
                              void* d_out, int out_size) {
    const float* x      = (const float*)d_in[0];   // [2,1024,768]
    const float* gate_w = (const float*)d_in[1];   // [768,8]
    const float* w_gate = (const float*)d_in[2];   // [8,768,2048]
    const float* w_up   = (const float*)d_in[3];   // [8,768,2048]
    const float* w_down = (const float*)d_in[4];   // [8,2048,768]
    float* out = (float*)d_out;

    k_reset<<<512, 256>>>(out, out_size);
    k_router<<<T_TOK / 8, 256>>>(x, gate_w);
    k_scatter<<<(T_TOK * 2 + 255) / 256, 256>>>();
    k_cvt_x<<<(T_TOK * D_MODEL / 4 + 255) / 256, 256>>>(x);

    {   // fused gate/up HMMA + SiLU
        dim3 grid(D_FF / 64, CAP / 128, NE);
        k_hmma_gu<<<grid, 256>>>(w_gate, w_up);
    }
    {   // down HMMA + weighted scatter-add
        dim3 grid(D_MODEL / 64, CAP / 128, NE);
        k_hmma_down<<<grid, 256>>>(w_down, out);
    }
}

// round 11
// speedup vs baseline: 2.1944x; 1.6320x over previous
#include <cuda_runtime.h>
#include <cuda_fp16.h>
#include <cstdint>
#include <math.h>

#define D_MODEL 768
#define D_FF    2048
#define NE      8
#define T_TOK   2048
#define CAP     2048

// ======================= scratch (__device__ globals) =======================
__device__ int   g_count[NE];
__device__ int   g_fill[NE];
__device__ int   g_rows[NE * CAP];
__device__ float g_wts [NE * CAP];
__device__ int   g_topi[T_TOK * 2];
__device__ float g_topw[T_TOK * 2];

__device__ __align__(16) __half g_x16[T_TOK * D_MODEL];
// h = silu(g)*u, fp16: [E][CAP][D_FF]
__device__ __align__(16) __half g_h16[(size_t)NE * CAP * D_FF];

// ======================= helpers =======================
__device__ __forceinline__ uint32_t smem_u32(const void* p) {
    uint32_t a;
    asm("{ .reg .u64 t; cvta.to.shared.u64 t, %1; cvt.u32.u64 %0, t; }" : "=r"(a) : "l"(p));
    return a;
}
__device__ __forceinline__ void ldsm4(uint32_t (&r)[4], uint32_t addr) {
    asm volatile("ldmatrix.sync.aligned.m8n8.x4.shared.b16 {%0,%1,%2,%3}, [%4];"
                 : "=r"(r[0]), "=r"(r[1]), "=r"(r[2]), "=r"(r[3]) : "r"(addr));
}
__device__ __forceinline__ void ldsm4t(uint32_t (&r)[4], uint32_t addr) {
    asm volatile("ldmatrix.sync.aligned.m8n8.x4.trans.shared.b16 {%0,%1,%2,%3}, [%4];"
                 : "=r"(r[0]), "=r"(r[1]), "=r"(r[2]), "=r"(r[3]) : "r"(addr));
}
// fp16 inputs, fp32 accumulate
__device__ __forceinline__ void mma16816(float (&d)[4], const uint32_t (&a)[4],
                                         uint32_t b0, uint32_t b1) {
    asm volatile(
        "mma.sync.aligned.m16n8k16.row.col.f32.f16.f16.f32 "
        "{%0,%1,%2,%3}, {%4,%5,%6,%7}, {%8,%9}, {%0,%1,%2,%3};"
        : "+f"(d[0]), "+f"(d[1]), "+f"(d[2]), "+f"(d[3])
        : "r"(a[0]), "r"(a[1]), "r"(a[2]), "r"(a[3]), "r"(b0), "r"(b1));
}

__device__ __forceinline__ uint32_t pack2h(__half a, __half b) {
    __half2 p = __halves2half2(a, b);
    return *reinterpret_cast<uint32_t*>(&p);
}
// 8 fp32 -> 8 fp16, packed as uint4
__device__ __forceinline__ uint4 cvt8h(const float4& f0, const float4& f1) {
    return make_uint4(
        pack2h(__float2half_rn(f0.x), __float2half_rn(f0.y)),
        pack2h(__float2half_rn(f0.z), __float2half_rn(f0.w)),
        pack2h(__float2half_rn(f1.x), __float2half_rn(f1.y)),
        pack2h(__float2half_rn(f1.z), __float2half_rn(f1.w)));
}

// ======================= small kernels =======================
__global__ void k_reset(float* __restrict__ out, int out_n) {
    int i = blockIdx.x * blockDim.x + threadIdx.x;
    if (i < NE) { g_count[i] = 0; g_fill[i] = 0; }
    for (int j = i; j < out_n; j += gridDim.x * blockDim.x) out[j] = 0.0f;
}

__global__ void k_router(const float* __restrict__ x, const float* __restrict__ gw) {
    int t = blockIdx.x * (blockDim.x >> 5) + (threadIdx.x >> 5);
    int lane = threadIdx.x & 31;
    if (t >= T_TOK) return;
    const float* xr = x + (size_t)t * D_MODEL;
    float acc[NE];
#pragma unroll
    for (int e = 0; e < NE; e++) acc[e] = 0.0f;
    for (int d = lane; d < D_MODEL; d += 32) {
        float xv = xr[d];
        const float* g = gw + (size_t)d * NE;
#pragma unroll
        for (int e = 0; e < NE; e++) acc[e] += xv * g[e];
    }
#pragma unroll
    for (int off = 16; off > 0; off >>= 1)
#pragma unroll
        for (int e = 0; e < NE; e++) acc[e] += __shfl_xor_sync(0xFFFFFFFFu, acc[e], off);

    if (lane == 0) {
        int i0 = 0;
#pragma unroll
        for (int e = 1; e < NE; e++) if (acc[e] > acc[i0]) i0 = e;
        int i1 = -1; float b = -1e30f;
#pragma unroll
        for (int e = 0; e < NE; e++) if (e != i0 && acc[e] > b) { b = acc[e]; i1 = e; }
        float w1 = expf(acc[i1] - acc[i0]);
        float s  = 1.0f + w1;
        g_topi[t * 2 + 0] = i0;  g_topw[t * 2 + 0] = 1.0f / s;
        g_topi[t * 2 + 1] = i1;  g_topw[t * 2 + 1] = w1 / s;
        atomicAdd(&g_count[i0], 1);
        atomicAdd(&g_count[i1], 1);
    }
}

__global__ void k_scatter() {
    int idx = blockIdx.x * blockDim.x + threadIdx.x;
    if (idx >= T_TOK * 2) return;
    int e = g_topi[idx];
    int p = atomicAdd(&g_fill[e], 1);
    g_rows[e * CAP + p] = idx >> 1;
    g_wts [e * CAP + p] = g_topw[idx];
}

// vectorized: 4 fp32 -> 4 fp16 per thread
__global__ void k_cvt_x(const float* __restrict__ x) {
    int i = blockIdx.x * blockDim.x + threadIdx.x;
    if (i >= T_TOK * D_MODEL / 4) return;
    float4 f = reinterpret_cast<const float4*>(x)[i];
    reinterpret_cast<uint2*>(g_x16)[i] = make_uint2(
        pack2h(__float2half_rn(f.x), __float2half_rn(f.y)),
        pack2h(__float2half_rn(f.z), __float2half_rn(f.w)));
}

// ======================= HMMA GEMM kernels =======================
// Tile: M=128 x N=64, K-chunk 32. 256 threads = 8 warps in 4(m) x 2(n).
// A smem row stride 40 fp16 (80B), B 72 fp16 (144B) -> ldmatrix conflict-free.
#define SA 40
#define SB 72

// h = silu(x@Wg) * (x@Wu)  (weights read fp32 [k][n] native layout, converted inline)
__global__ void __launch_bounds__(256) k_hmma_gu(
    const float* __restrict__ wg, const float* __restrict__ wu)
{
    int e   = blockIdx.z;
    int cnt = g_count[e];
    int r0  = blockIdx.y * 128;
    if (r0 >= cnt) return;
    int n0  = blockIdx.x * 64;

    __shared__ __half sA[128 * SA];
    __shared__ __half sGh[32 * SB];
    __shared__ __half sUh[32 * SB];

    int tid = threadIdx.x, lane = tid & 31, wid = tid >> 5;
    int wm = wid >> 1, wn = wid & 1;

    // --- loader setup ---
    int arow = tid >> 1, ahalf = tid & 1;
    int slotA = r0 + arow;
    int tok = (slotA < cnt) ? g_rows[e * CAP + slotA] : 0;
    const __half* pA = g_x16 + (size_t)tok * D_MODEL + ahalf * 16;
    __half* dA = sA + arow * SA + ahalf * 16;

    int brow = tid >> 3, bq = tid & 7;      // 32 k-rows x 8 col-quads
    const float* pG = wg + (size_t)e * D_MODEL * D_FF + (size_t)brow * D_FF + n0 + bq * 8;
    const float* pU = wu + (size_t)e * D_MODEL * D_FF + (size_t)brow * D_FF + n0 + bq * 8;
    uint4* dGh = (uint4*)(sGh + brow * SB + bq * 8);
    uint4* dUh = (uint4*)(sUh + brow * SB + bq * 8);

    uint32_t bA  = smem_u32(sA);
    uint32_t bGh = smem_u32(sGh);
    uint32_t bUh = smem_u32(sUh);

    float ag[2][4][4], au[2][4][4];
#pragma unroll
    for (int i = 0; i < 2; i++)
#pragma unroll
        for (int j = 0; j < 4; j++)
#pragma unroll
            for (int q = 0; q < 4; q++) { ag[i][j][q] = 0.0f; au[i][j][q] = 0.0f; }

    for (int c = 0; c < D_MODEL / 32; c++) {      // 24 chunks
        int k0 = c * 32;
        if (c > 0) __syncthreads();
        // A fill: 16 fp16 per thread
        *(uint4*)dA       = *(const uint4*)(pA + k0);
        *(uint4*)(dA + 8) = *(const uint4*)(pA + k0 + 8);
        // B fill: 8 fp32 -> fp16 per matrix
        {
            const float* s = pG + (size_t)k0 * D_FF;
            float4 f0 = *(const float4*)s, f1 = *(const float4*)(s + 4);
            *dGh = cvt8h(f0, f1);
        }
        {
            const float* s = pU + (size_t)k0 * D_FF;
            float4 f0 = *(const float4*)s, f1 = *(const float4*)(s + 4);
            *dUh = cvt8h(f0, f1);
        }
        __syncthreads();

#pragma unroll
        for (int kk = 0; kk < 32; kk += 16) {
            uint32_t ah[2][4];
#pragma unroll
            for (int mf = 0; mf < 2; mf++) {
                uint32_t ro = wm * 32 + mf * 16 + (lane & 15);
                uint32_t co = kk + (lane >> 4) * 8;
                ldsm4(ah[mf], bA + (ro * SA + co) * 2);
            }
            uint32_t kr = kk + (lane & 7) + ((lane >> 4) & 1) * 8;
            uint32_t ncol = wn * 32 + ((lane >> 3) & 1) * 8;
            // ---- gate ----
            {
                uint32_t bh[4][2], r4[4];
#pragma unroll
                for (int p = 0; p < 2; p++) {
                    uint32_t off = (kr * SB + ncol + p * 16) * 2;
                    ldsm4t(r4, bGh + off);
                    bh[p*2][0] = r4[0]; bh[p*2+1][0] = r4[1]; bh[p*2][1] = r4[2]; bh[p*2+1][1] = r4[3];
                }
#pragma unroll
                for (int mf = 0; mf < 2; mf++)
#pragma unroll
                    for (int nf = 0; nf < 4; nf++)
                        mma16816(ag[mf][nf], ah[mf], bh[nf][0], bh[nf][1]);
            }
            // ---- up ----
            {
                uint32_t bh[4][2], r4[4];
#pragma unroll
                for (int p = 0; p < 2; p++) {
                    uint32_t off = (kr * SB + ncol + p * 16) * 2;
                    ldsm4t(r4, bUh + off);
                    bh[p*2][0] = r4[0]; bh[p*2+1][0] = r4[1]; bh[p*2][1] = r4[2]; bh[p*2+1][1] = r4[3];
                }
#pragma unroll
                for (int mf = 0; mf < 2; mf++)
#pragma unroll
                    for (int nf = 0; nf < 4; nf++)
                        mma16816(au[mf][nf], ah[mf], bh[nf][0], bh[nf][1]);
            }
        }
    }

    // ---- epilogue: h = silu(g)*u -> fp16 ----
    int lr = lane >> 2, lc = (lane & 3) * 2;
#pragma unroll
    for (int mf = 0; mf < 2; mf++)
#pragma unroll
        for (int half = 0; half < 2; half++) {
            int slot = r0 + wm * 32 + mf * 16 + lr + half * 8;
            if (slot >= cnt) continue;
            size_t base = ((size_t)e * CAP + slot) * D_FF + n0 + wn * 32 + lc;
#pragma unroll
            for (int nf = 0; nf < 4; nf++) {
                float g0 = ag[mf][nf][half * 2 + 0], g1 = ag[mf][nf][half * 2 + 1];
                float u0 = au[mf][nf][half * 2 + 0], u1 = au[mf][nf][half * 2 + 1];
                float h0 = (g0 / (1.0f + __expf(-g0))) * u0;
                float h1 = (g1 / (1.0f + __expf(-g1))) * u1;
                *(__half2*)(g_h16 + base + nf * 8) =
                    __halves2half2(__float2half_rn(h0), __float2half_rn(h1));
            }
        }
}

// out[token] += gate_wt * (h @ Wd)
__global__ void __launch_bounds__(256) k_hmma_down(
    const float* __restrict__ wd, float* __restrict__ out)
{
    int e   = blockIdx.z;
    int cnt = g_count[e];
    int r0  = blockIdx.y * 128;
    if (r0 >= cnt) return;
    int n0  = blockIdx.x * 64;

    __shared__ __half sA[128 * SA];
    __shared__ __half sBh[32 * SB];

    int tid = threadIdx.x, lane = tid & 31, wid = tid >> 5;
    int wm = wid >> 1, wn = wid & 1;

    int arow = tid >> 1, ahalf = tid & 1;
    int slotA = r0 + arow;
    int asafe = (slotA < cnt) ? slotA : 0;
    size_t hrow = ((size_t)e * CAP + asafe) * D_FF + ahalf * 16;
    const __half* pA = g_h16 + hrow;
    __half* dA = sA + arow * SA + ahalf * 16;

    int brow = tid >> 3, bq = tid & 7;
    const float* pB = wd + (size_t)e * D_FF * D_MODEL + (size_t)brow * D_MODEL + n0 + bq * 8;
    uint4* dBh = (uint4*)(sBh + brow * SB + bq * 8);

    uint32_t bA  = smem_u32(sA);
    uint32_t bBh = smem_u32(sBh);

    float ac[2][4][4];
#pragma unroll
    for (int i = 0; i < 2; i++)
#pragma unroll
        for (int j = 0; j < 4; j++)
#pragma unroll
            for (int q = 0; q < 4; q++) ac[i][j][q] = 0.0f;

    for (int c = 0; c < D_FF / 32; c++) {         // 64 chunks
        int k0 = c * 32;
        if (c > 0) __syncthreads();
        *(uint4*)dA       = *(const uint4*)(pA + k0);
        *(uint4*)(dA + 8) = *(const uint4*)(pA + k0 + 8);
        {
            const float* s = pB + (size_t)k0 * D_MODEL;
            float4 f0 = *(const float4*)s, f1 = *(const float4*)(s + 4);
            *dBh = cvt8h(f0, f1);
        }
        __syncthreads();

#pragma unroll
        for (int kk = 0; kk < 32; kk += 16) {
            uint32_t ah[2][4];
#pragma unroll
            for (int mf = 0; mf < 2; mf++) {
                uint32_t ro = wm * 32 + mf * 16 + (lane & 15);
                uint32_t co = kk + (lane >> 4) * 8;
                ldsm4(ah[mf], bA + (ro * SA + co) * 2);
            }
            uint32_t kr = kk + (lane & 7) + ((lane >> 4) & 1) * 8;
            uint32_t ncol = wn * 32 + ((lane >> 3) & 1) * 8;
            uint32_t bh[4][2], r4[4];
#pragma unroll
            for (int p = 0; p < 2; p++) {
                uint32_t off = (kr * SB + ncol + p * 16) * 2;
                ldsm4t(r4, bBh + off);
                bh[p*2][0] = r4[0]; bh[p*2+1][0] = r4[1]; bh[p*2][1] = r4[2]; bh[p*2+1][1] = r4[3];
            }
#pragma unroll
            for (int mf = 0; mf < 2; mf++)
#pragma unroll
                for (int nf = 0; nf < 4; nf++)
                    mma16816(ac[mf][nf], ah[mf], bh[nf][0], bh[nf][1]);
        }
    }

    // ---- epilogue: weighted atomic scatter-add ----
    int lr = lane >> 2, lc = (lane & 3) * 2;
#pragma unroll
    for (int mf = 0; mf < 2; mf++)
#pragma unroll
        for (int half = 0; half < 2; half++) {
            int slot = r0 + wm * 32 + mf * 16 + lr + half * 8;
            if (slot >= cnt) continue;
            int   tok = g_rows[e * CAP + slot];
            float w   = g_wts [e * CAP + slot];
            float* orow = out + (size_t)tok * D_MODEL + n0 + wn * 32 + lc;
#pragma unroll
            for (int nf = 0; nf < 4; nf++) {
                atomicAdd(&orow[nf * 8 + 0], ac[mf][nf][half * 2 + 0] * w);
                atomicAdd(&orow[nf * 8 + 1], ac[mf][nf][half * 2 + 1] * w);
            }
        }
}

// ======================= launch =======================
extern "C" void kernel_launch(void* const* d_in, const int* in_sizes, int n_in,
                              void* d_out, int out_size) {
    const float* x      = (const float*)d_in[0];   // [2,1024,768]
    const float* gate_w = (const float*)d_in[1];   // [768,8]
    const float* w_gate = (const float*)d_in[2];   // [8,768,2048]
    const float* w_up   = (const float*)d_in[3];   // [8,768,2048]
    const float* w_down = (const float*)d_in[4];   // [8,2048,768]
    float* out = (float*)d_out;

    k_reset<<<512, 256>>>(out, out_size);
    k_router<<<T_TOK / 8, 256>>>(x, gate_w);
    k_scatter<<<(T_TOK * 2 + 255) / 256, 256>>>();
    k_cvt_x<<<(T_TOK * D_MODEL / 4 + 255) / 256, 256>>>(x);

    {   // fused gate/up HMMA + SiLU
        dim3 grid(D_FF / 64, CAP / 128, NE);
        k_hmma_gu<<<grid, 256>>>(w_gate, w_up);
    }
    {   // down HMMA + weighted scatter-add
        dim3 grid(D_MODEL / 64, CAP / 128, NE);
        k_hmma_down<<<grid, 256>>>(w_down, out);
    }
}